// round 1
// baseline (speedup 1.0000x reference)
#include <cuda_runtime.h>
#include <math.h>

#define NNODES 50000
#define NEDGES 1600000
#define FDIM_IN 128
#define HID 256
#define NCLS 40

// -------- scratch (no allocation allowed; __device__ globals) --------
__device__ int   g_deg[NNODES];
__device__ float g_inv[NNODES];
__device__ float g_norm[NEDGES];
__device__ float g_bufA[(size_t)NNODES * HID];   // aggregation buffer
__device__ float g_bufB[(size_t)NNODES * HID];   // hidden activations
__device__ float g_t4[(size_t)NNODES * NCLS];    // h3 @ W4
__device__ float g_agg4[(size_t)NNODES * NCLS];  // aggregated logits

// vector atomic add (sm_90+): 4 floats per L2 atomic op
__device__ __forceinline__ void redAdd4(float4* addr, float4 v) {
    asm volatile("red.global.add.v4.f32 [%0], {%1, %2, %3, %4};"
                 :: "l"(addr), "f"(v.x), "f"(v.y), "f"(v.z), "f"(v.w)
                 : "memory");
}

// -------- degree / normalization --------
__global__ void k_zero_deg(int n) {
    int i = blockIdx.x * blockDim.x + threadIdx.x;
    if (i < n) g_deg[i] = 0;
}

__global__ void k_deg(const int* __restrict__ dst, int E) {
    int e = blockIdx.x * blockDim.x + threadIdx.x;
    if (e < E) atomicAdd(&g_deg[dst[e]], 1);
}

__global__ void k_inv(int n) {
    int i = blockIdx.x * blockDim.x + threadIdx.x;
    if (i < n) g_inv[i] = rsqrtf((float)g_deg[i] + 1.0f);
}

__global__ void k_norm(const int* __restrict__ src, const int* __restrict__ dst, int E) {
    int e = blockIdx.x * blockDim.x + threadIdx.x;
    if (e < E) g_norm[e] = g_inv[src[e]] * g_inv[dst[e]];
}

// -------- self-loop init: agg[n,:] = h[n,:] * inv[n]^2  (F4 = F/4) --------
__global__ void k_selfinit(const float* __restrict__ h, float* __restrict__ agg,
                           int n, int F4) {
    int idx = blockIdx.x * blockDim.x + threadIdx.x;
    int total = n * F4;
    if (idx >= total) return;
    int node = idx / F4;
    float s = g_inv[node]; s *= s;
    float4 v = ((const float4*)h)[idx];
    v.x *= s; v.y *= s; v.z *= s; v.w *= s;
    ((float4*)agg)[idx] = v;
}

// -------- edge aggregation, warp per edge (F4 = F/4, >= 32) --------
template<int F4>
__global__ void k_edge_agg(const int* __restrict__ src, const int* __restrict__ dst,
                           const float* __restrict__ h, float* __restrict__ agg, int E) {
    int warp = (blockIdx.x * blockDim.x + threadIdx.x) >> 5;
    int lane = threadIdx.x & 31;
    if (warp >= E) return;
    int s = __ldg(src + warp);
    int d = __ldg(dst + warp);
    float w = __ldg(g_norm + warp);
    const float4* hp = (const float4*)h + (size_t)s * F4;
    float4* ap = (float4*)agg + (size_t)d * F4;
#pragma unroll
    for (int c = lane; c < F4; c += 32) {
        float4 v = __ldg(hp + c);
        v.x *= w; v.y *= w; v.z *= w; v.w *= w;
        redAdd4(ap + c, v);
    }
}

// -------- edge aggregation for 40-wide (10 float4 chunks per edge) --------
__global__ void k_edge_agg40(const int* __restrict__ src, const int* __restrict__ dst,
                             const float* __restrict__ h, float* __restrict__ agg, int E) {
    int idx = blockIdx.x * blockDim.x + threadIdx.x;
    int total = E * 10;
    if (idx >= total) return;
    int e = idx / 10;
    int c = idx - e * 10;
    int s = __ldg(src + e);
    int d = __ldg(dst + e);
    float w = __ldg(g_norm + e);
    float4 v = __ldg((const float4*)h + (size_t)s * 10 + c);
    v.x *= w; v.y *= w; v.z *= w; v.w *= w;
    redAdd4((float4*)agg + (size_t)d * 10 + c, v);
}

// -------- SGEMM: C[M,Nc] = A[M,K] @ B[K,Nc] (+bias)(+relu) --------
// BM=BN=128, BK=8, 256 threads, 8x8 per thread. Requires K%8==0, Nc%128==0.
__global__ void __launch_bounds__(256, 2)
k_sgemm(const float* __restrict__ A, const float* __restrict__ B,
        const float* __restrict__ bias, float* __restrict__ C,
        int M, int K, int Nc, int relu) {
    const int BM = 128, BN = 128, BK = 8, TM = 8, TN = 8;
    __shared__ float As[BK][BM];
    __shared__ float Bs[BK][BN];
    int bm = blockIdx.y * BM;
    int bn = blockIdx.x * BN;
    int tid = threadIdx.x;

    int arow = tid >> 1;            // 0..127
    int acol = (tid & 1) * 4;       // 0 or 4
    int brow = tid >> 5;            // 0..7
    int bcol = (tid & 31) * 4;      // 0..124

    int tr = (tid >> 4) * TM;       // 0..120
    int tc = (tid & 15) * TN;       // 0..120

    float acc[TM][TN];
#pragma unroll
    for (int i = 0; i < TM; i++)
#pragma unroll
        for (int j = 0; j < TN; j++) acc[i][j] = 0.0f;

    for (int k0 = 0; k0 < K; k0 += BK) {
        int gr = bm + arow;
        float4 av = make_float4(0.f, 0.f, 0.f, 0.f);
        if (gr < M) av = *(const float4*)(A + (size_t)gr * K + k0 + acol);
        As[acol + 0][arow] = av.x;
        As[acol + 1][arow] = av.y;
        As[acol + 2][arow] = av.z;
        As[acol + 3][arow] = av.w;
        float4 bv = *(const float4*)(B + (size_t)(k0 + brow) * Nc + bn + bcol);
        *(float4*)&Bs[brow][bcol] = bv;
        __syncthreads();

#pragma unroll
        for (int k = 0; k < BK; k++) {
            float ar[TM], br[TN];
#pragma unroll
            for (int i = 0; i < TM; i++) ar[i] = As[k][tr + i];
#pragma unroll
            for (int j = 0; j < TN; j++) br[j] = Bs[k][tc + j];
#pragma unroll
            for (int i = 0; i < TM; i++)
#pragma unroll
                for (int j = 0; j < TN; j++) acc[i][j] += ar[i] * br[j];
        }
        __syncthreads();
    }

#pragma unroll
    for (int i = 0; i < TM; i++) {
        int gr = bm + tr + i;
        if (gr >= M) continue;
#pragma unroll
        for (int j = 0; j < TN; j += 4) {
            float4 v;
            v.x = acc[i][j + 0] + bias[bn + tc + j + 0];
            v.y = acc[i][j + 1] + bias[bn + tc + j + 1];
            v.z = acc[i][j + 2] + bias[bn + tc + j + 2];
            v.w = acc[i][j + 3] + bias[bn + tc + j + 3];
            if (relu) {
                v.x = fmaxf(v.x, 0.f); v.y = fmaxf(v.y, 0.f);
                v.z = fmaxf(v.z, 0.f); v.w = fmaxf(v.w, 0.f);
            }
            *(float4*)(C + (size_t)gr * Nc + bn + tc + j) = v;
        }
    }
}

// -------- GEMM for layer 4: t4[M,40] = A[M,256] @ W4[256,40] (no bias) --------
// block = 160 threads, 4 rows x 40 cols each, W4 staged in smem.
__global__ void __launch_bounds__(160)
k_gemm40(const float* __restrict__ A, const float* __restrict__ W,
         float* __restrict__ C, int M) {
    __shared__ float Ws[256 * 40];   // 40 KB
    __shared__ float Asm[4 * 256];   // 4 KB
    int tid = threadIdx.x;
    int row0 = blockIdx.x * 4;

    for (int i = tid; i < 256 * 40; i += 160) Ws[i] = W[i];
    for (int i = tid; i < 4 * 256; i += 160) {
        int r = i >> 8;
        if (row0 + r < M) Asm[i] = A[(size_t)(row0 + r) * 256 + (i & 255)];
    }
    __syncthreads();

    int r = tid / 40;
    int c = tid - r * 40;
    if (row0 + r >= M) return;
    float acc = 0.0f;
    const float* a = &Asm[r * 256];
#pragma unroll 8
    for (int k = 0; k < 256; k++) acc += a[k] * Ws[k * 40 + c];
    C[(size_t)(row0 + r) * 40 + c] = acc;
}

// -------- out = log_softmax(agg4 + b4), warp per row (40 cols) --------
__global__ void k_logsoftmax40(const float* __restrict__ b4, float* __restrict__ out, int n) {
    int warp = (blockIdx.x * blockDim.x + threadIdx.x) >> 5;
    int lane = threadIdx.x & 31;
    if (warp >= n) return;
    const float* row = g_agg4 + (size_t)warp * 40;
    float v0 = row[lane] + b4[lane];
    float v1 = (lane < 8) ? row[32 + lane] + b4[32 + lane] : -INFINITY;
    float m = fmaxf(v0, v1);
#pragma unroll
    for (int o = 16; o > 0; o >>= 1) m = fmaxf(m, __shfl_xor_sync(0xFFFFFFFF, m, o));
    float s = __expf(v0 - m) + ((lane < 8) ? __expf(v1 - m) : 0.0f);
#pragma unroll
    for (int o = 16; o > 0; o >>= 1) s += __shfl_xor_sync(0xFFFFFFFF, s, o);
    float l = m + __logf(s);
    out[(size_t)warp * 40 + lane] = v0 - l;
    if (lane < 8) out[(size_t)warp * 40 + 32 + lane] = v1 - l;
}

// ---------------------------------------------------------------
extern "C" void kernel_launch(void* const* d_in, const int* in_sizes, int n_in,
                              void* d_out, int out_size) {
    const float* x  = (const float*)d_in[0];
    const int*   ei = (const int*)d_in[1];
    const float* W1 = (const float*)d_in[2]; const float* b1 = (const float*)d_in[3];
    const float* W2 = (const float*)d_in[4]; const float* b2 = (const float*)d_in[5];
    const float* W3 = (const float*)d_in[6]; const float* b3 = (const float*)d_in[7];
    const float* W4 = (const float*)d_in[8]; const float* b4 = (const float*)d_in[9];
    float* out = (float*)d_out;

    int N = in_sizes[0] / FDIM_IN;
    int E = in_sizes[1] / 2;
    const int* src = ei;
    const int* dst = ei + E;

    void *pA, *pB, *pt4, *pagg4;
    cudaGetSymbolAddress(&pA, g_bufA);
    cudaGetSymbolAddress(&pB, g_bufB);
    cudaGetSymbolAddress(&pt4, g_t4);
    cudaGetSymbolAddress(&pagg4, g_agg4);
    float* bufA = (float*)pA;
    float* bufB = (float*)pB;
    float* t4   = (float*)pt4;
    float* agg4 = (float*)pagg4;

    const int TB = 256;
    // --- degree + norms ---
    k_zero_deg<<<(N + TB - 1) / TB, TB>>>(N);
    k_deg<<<(E + TB - 1) / TB, TB>>>(dst, E);
    k_inv<<<(N + TB - 1) / TB, TB>>>(N);
    k_norm<<<(E + TB - 1) / TB, TB>>>(src, dst, E);

    dim3 gemm_grid(HID / 128, (N + 127) / 128);

    // --- Layer 1: aggregate x (128-dim) first, then GEMM+ReLU ---
    k_selfinit<<<(N * 32 + TB - 1) / TB, TB>>>(x, bufA, N, 32);
    k_edge_agg<32><<<(E + 7) / 8, TB>>>(src, dst, x, bufA, E);
    k_sgemm<<<gemm_grid, 256>>>(bufA, W1, b1, bufB, N, FDIM_IN, HID, 1);

    // --- Layer 2: aggregate h1 (256-dim), GEMM+ReLU ---
    k_selfinit<<<(N * 64 + TB - 1) / TB, TB>>>(bufB, bufA, N, 64);
    k_edge_agg<64><<<(E + 7) / 8, TB>>>(src, dst, bufB, bufA, E);
    k_sgemm<<<gemm_grid, 256>>>(bufA, W2, b2, bufB, N, HID, HID, 1);

    // --- Layer 3 ---
    k_selfinit<<<(N * 64 + TB - 1) / TB, TB>>>(bufB, bufA, N, 64);
    k_edge_agg<64><<<(E + 7) / 8, TB>>>(src, dst, bufB, bufA, E);
    k_sgemm<<<gemm_grid, 256>>>(bufA, W3, b3, bufB, N, HID, HID, 1);

    // --- Layer 4: GEMM to 40 dims first, then aggregate (40-dim) ---
    k_gemm40<<<(N + 3) / 4, 160>>>(bufB, W4, t4, N);
    k_selfinit<<<(N * 10 + TB - 1) / TB, TB>>>(t4, agg4, N, 10);
    k_edge_agg40<<<(E * 10 + TB - 1) / TB, TB>>>(src, dst, t4, agg4, E);

    // --- log_softmax ---
    k_logsoftmax40<<<(N * 32 + TB - 1) / TB, TB>>>(b4, out, N);
}

// round 2
// speedup vs baseline: 1.1759x; 1.1759x over previous
#include <cuda_runtime.h>
#include <math.h>

#define NNODES 50000
#define NEDGES 1600000
#define FDIM_IN 128
#define HID 256
#define NCLS 40

// -------- scratch (no allocation allowed; __device__ globals) --------
__device__ int   g_deg[NNODES];
__device__ float g_inv[NNODES];
__device__ int   g_rowstart[NNODES + 1];
__device__ int   g_cursor[NNODES];
__device__ int   g_csr_src[NEDGES];
__device__ float g_csr_w[NEDGES];
__device__ float g_bufA[(size_t)NNODES * HID];   // aggregation buffer
__device__ float g_bufB[(size_t)NNODES * HID];   // hidden activations
__device__ float g_t4[(size_t)NNODES * NCLS];    // h3 @ W4
__device__ float g_agg4[(size_t)NNODES * NCLS];  // aggregated logits

// -------- degree / normalization / CSR build --------
__global__ void k_zero_deg(int n) {
    int i = blockIdx.x * blockDim.x + threadIdx.x;
    if (i < n) g_deg[i] = 0;
}

__global__ void k_deg(const int* __restrict__ dst, int E) {
    int e = blockIdx.x * blockDim.x + threadIdx.x;
    if (e < E) atomicAdd(&g_deg[dst[e]], 1);
}

__global__ void k_inv(int n) {
    int i = blockIdx.x * blockDim.x + threadIdx.x;
    if (i < n) g_inv[i] = rsqrtf((float)g_deg[i] + 1.0f);
}

// single-block exclusive scan of g_deg -> g_rowstart, g_cursor
__global__ void __launch_bounds__(1024)
k_scan(int n) {
    __shared__ int sums[1024];
    int tid = threadIdx.x;
    int chunk = (n + 1023) / 1024;
    int beg = tid * chunk;
    int end = min(beg + chunk, n);
    int s = 0;
    for (int i = beg; i < end; i++) s += g_deg[i];
    int mysum = s;
    sums[tid] = s;
    __syncthreads();
    for (int off = 1; off < 1024; off <<= 1) {
        int t = (tid >= off) ? sums[tid - off] : 0;
        __syncthreads();
        sums[tid] += t;
        __syncthreads();
    }
    int base = sums[tid] - mysum;   // exclusive prefix for this chunk
    for (int i = beg; i < end; i++) {
        int d = g_deg[i];
        g_rowstart[i] = base;
        g_cursor[i]   = base;
        base += d;
    }
    if (tid == 1023) g_rowstart[n] = sums[1023];
}

__global__ void k_scatter(const int* __restrict__ src, const int* __restrict__ dst, int E) {
    int e = blockIdx.x * blockDim.x + threadIdx.x;
    if (e >= E) return;
    int s = src[e];
    int d = dst[e];
    int pos = atomicAdd(&g_cursor[d], 1);
    g_csr_src[pos] = s;
    g_csr_w[pos]   = g_inv[s] * g_inv[d];
}

// -------- gather-based aggregation: one block per node, thread per column --------
// agg[n,f] = h[n,f]*inv[n]^2 + sum_j w_j * h[src_j, f]
template<int F, int BLK>
__global__ void __launch_bounds__(BLK)
k_gather_agg(const float* __restrict__ h, float* __restrict__ agg) {
    int node = blockIdx.x;
    int f = threadIdx.x;
    if (f >= F) return;
    float iv = g_inv[node];
    float acc = __ldg(h + (size_t)node * F + f) * iv * iv;
    int j   = g_rowstart[node];
    int end = g_rowstart[node + 1];
    for (; j + 4 <= end; j += 4) {
        int   s0 = g_csr_src[j],   s1 = g_csr_src[j+1];
        int   s2 = g_csr_src[j+2], s3 = g_csr_src[j+3];
        float w0 = g_csr_w[j],     w1 = g_csr_w[j+1];
        float w2 = g_csr_w[j+2],   w3 = g_csr_w[j+3];
        float v0 = __ldg(h + (size_t)s0 * F + f);
        float v1 = __ldg(h + (size_t)s1 * F + f);
        float v2 = __ldg(h + (size_t)s2 * F + f);
        float v3 = __ldg(h + (size_t)s3 * F + f);
        acc += w0 * v0;
        acc += w1 * v1;
        acc += w2 * v2;
        acc += w3 * v3;
    }
    for (; j < end; j++) {
        int   s = g_csr_src[j];
        float w = g_csr_w[j];
        acc += w * __ldg(h + (size_t)s * F + f);
    }
    agg[(size_t)node * F + f] = acc;
}

// -------- SGEMM: C[M,Nc] = A[M,K] @ B[K,Nc] (+bias)(+relu) --------
// BM=BN=128, BK=8, 256 threads, 8x8 per thread. Requires K%8==0, Nc%128==0.
__global__ void __launch_bounds__(256, 2)
k_sgemm(const float* __restrict__ A, const float* __restrict__ B,
        const float* __restrict__ bias, float* __restrict__ C,
        int M, int K, int Nc, int relu) {
    const int BM = 128, BN = 128, BK = 8, TM = 8, TN = 8;
    __shared__ float As[BK][BM];
    __shared__ float Bs[BK][BN];
    int bm = blockIdx.y * BM;
    int bn = blockIdx.x * BN;
    int tid = threadIdx.x;

    int arow = tid >> 1;            // 0..127
    int acol = (tid & 1) * 4;       // 0 or 4
    int brow = tid >> 5;            // 0..7
    int bcol = (tid & 31) * 4;      // 0..124

    int tr = (tid >> 4) * TM;       // 0..120
    int tc = (tid & 15) * TN;       // 0..120

    float acc[TM][TN];
#pragma unroll
    for (int i = 0; i < TM; i++)
#pragma unroll
        for (int j = 0; j < TN; j++) acc[i][j] = 0.0f;

    for (int k0 = 0; k0 < K; k0 += BK) {
        int gr = bm + arow;
        float4 av = make_float4(0.f, 0.f, 0.f, 0.f);
        if (gr < M) av = *(const float4*)(A + (size_t)gr * K + k0 + acol);
        As[acol + 0][arow] = av.x;
        As[acol + 1][arow] = av.y;
        As[acol + 2][arow] = av.z;
        As[acol + 3][arow] = av.w;
        float4 bv = *(const float4*)(B + (size_t)(k0 + brow) * Nc + bn + bcol);
        *(float4*)&Bs[brow][bcol] = bv;
        __syncthreads();

#pragma unroll
        for (int k = 0; k < BK; k++) {
            float ar[TM], br[TN];
#pragma unroll
            for (int i = 0; i < TM; i++) ar[i] = As[k][tr + i];
#pragma unroll
            for (int j = 0; j < TN; j++) br[j] = Bs[k][tc + j];
#pragma unroll
            for (int i = 0; i < TM; i++)
#pragma unroll
                for (int j = 0; j < TN; j++) acc[i][j] += ar[i] * br[j];
        }
        __syncthreads();
    }

#pragma unroll
    for (int i = 0; i < TM; i++) {
        int gr = bm + tr + i;
        if (gr >= M) continue;
#pragma unroll
        for (int j = 0; j < TN; j += 4) {
            float4 v;
            v.x = acc[i][j + 0] + bias[bn + tc + j + 0];
            v.y = acc[i][j + 1] + bias[bn + tc + j + 1];
            v.z = acc[i][j + 2] + bias[bn + tc + j + 2];
            v.w = acc[i][j + 3] + bias[bn + tc + j + 3];
            if (relu) {
                v.x = fmaxf(v.x, 0.f); v.y = fmaxf(v.y, 0.f);
                v.z = fmaxf(v.z, 0.f); v.w = fmaxf(v.w, 0.f);
            }
            *(float4*)(C + (size_t)gr * Nc + bn + tc + j) = v;
        }
    }
}

// -------- GEMM for layer 4: t4[M,40] = A[M,256] @ W4[256,40] (no bias) --------
__global__ void __launch_bounds__(160)
k_gemm40(const float* __restrict__ A, const float* __restrict__ W,
         float* __restrict__ C, int M) {
    __shared__ float Ws[256 * 40];   // 40 KB
    __shared__ float Asm[4 * 256];   // 4 KB
    int tid = threadIdx.x;
    int row0 = blockIdx.x * 4;

    for (int i = tid; i < 256 * 40; i += 160) Ws[i] = W[i];
    for (int i = tid; i < 4 * 256; i += 160) {
        int r = i >> 8;
        if (row0 + r < M) Asm[i] = A[(size_t)(row0 + r) * 256 + (i & 255)];
    }
    __syncthreads();

    int r = tid / 40;
    int c = tid - r * 40;
    if (row0 + r >= M) return;
    float acc = 0.0f;
    const float* a = &Asm[r * 256];
#pragma unroll 8
    for (int k = 0; k < 256; k++) acc += a[k] * Ws[k * 40 + c];
    C[(size_t)(row0 + r) * 40 + c] = acc;
}

// -------- out = log_softmax(agg4 + b4), warp per row (40 cols) --------
__global__ void k_logsoftmax40(const float* __restrict__ b4, float* __restrict__ out, int n) {
    int warp = (blockIdx.x * blockDim.x + threadIdx.x) >> 5;
    int lane = threadIdx.x & 31;
    if (warp >= n) return;
    const float* row = g_agg4 + (size_t)warp * 40;
    float v0 = row[lane] + b4[lane];
    float v1 = (lane < 8) ? row[32 + lane] + b4[32 + lane] : -INFINITY;
    float m = fmaxf(v0, v1);
#pragma unroll
    for (int o = 16; o > 0; o >>= 1) m = fmaxf(m, __shfl_xor_sync(0xFFFFFFFF, m, o));
    float s = __expf(v0 - m) + ((lane < 8) ? __expf(v1 - m) : 0.0f);
#pragma unroll
    for (int o = 16; o > 0; o >>= 1) s += __shfl_xor_sync(0xFFFFFFFF, s, o);
    float l = m + __logf(s);
    out[(size_t)warp * 40 + lane] = v0 - l;
    if (lane < 8) out[(size_t)warp * 40 + 32 + lane] = v1 - l;
}

// ---------------------------------------------------------------
extern "C" void kernel_launch(void* const* d_in, const int* in_sizes, int n_in,
                              void* d_out, int out_size) {
    const float* x  = (const float*)d_in[0];
    const int*   ei = (const int*)d_in[1];
    const float* W1 = (const float*)d_in[2]; const float* b1 = (const float*)d_in[3];
    const float* W2 = (const float*)d_in[4]; const float* b2 = (const float*)d_in[5];
    const float* W3 = (const float*)d_in[6]; const float* b3 = (const float*)d_in[7];
    const float* W4 = (const float*)d_in[8]; const float* b4 = (const float*)d_in[9];
    float* out = (float*)d_out;

    int N = in_sizes[0] / FDIM_IN;
    int E = in_sizes[1] / 2;
    const int* src = ei;
    const int* dst = ei + E;

    void *pA, *pB, *pt4, *pagg4;
    cudaGetSymbolAddress(&pA, g_bufA);
    cudaGetSymbolAddress(&pB, g_bufB);
    cudaGetSymbolAddress(&pt4, g_t4);
    cudaGetSymbolAddress(&pagg4, g_agg4);
    float* bufA = (float*)pA;
    float* bufB = (float*)pB;
    float* t4   = (float*)pt4;
    float* agg4 = (float*)pagg4;

    const int TB = 256;
    // --- degree + norms + CSR (by destination) ---
    k_zero_deg<<<(N + TB - 1) / TB, TB>>>(N);
    k_deg<<<(E + TB - 1) / TB, TB>>>(dst, E);
    k_inv<<<(N + TB - 1) / TB, TB>>>(N);
    k_scan<<<1, 1024>>>(N);
    k_scatter<<<(E + TB - 1) / TB, TB>>>(src, dst, E);

    dim3 gemm_grid(HID / 128, (N + 127) / 128);

    // --- Layer 1: aggregate x (128-dim) first, then GEMM+ReLU ---
    k_gather_agg<FDIM_IN, FDIM_IN><<<N, FDIM_IN>>>(x, bufA);
    k_sgemm<<<gemm_grid, 256>>>(bufA, W1, b1, bufB, N, FDIM_IN, HID, 1);

    // --- Layer 2: aggregate h1 (256-dim), GEMM+ReLU ---
    k_gather_agg<HID, HID><<<N, HID>>>(bufB, bufA);
    k_sgemm<<<gemm_grid, 256>>>(bufA, W2, b2, bufB, N, HID, HID, 1);

    // --- Layer 3 ---
    k_gather_agg<HID, HID><<<N, HID>>>(bufB, bufA);
    k_sgemm<<<gemm_grid, 256>>>(bufA, W3, b3, bufB, N, HID, HID, 1);

    // --- Layer 4: GEMM to 40 dims first, then aggregate (40-dim) ---
    k_gemm40<<<(N + 3) / 4, 160>>>(bufB, W4, t4, N);
    k_gather_agg<NCLS, 64><<<N, 64>>>(t4, agg4);

    // --- log_softmax ---
    k_logsoftmax40<<<(N * 32 + TB - 1) / TB, TB>>>(b4, out, N);
}

// round 3
// speedup vs baseline: 1.6472x; 1.4008x over previous
#include <cuda_runtime.h>
#include <math.h>
#include <stdint.h>

#define NNODES 50000
#define NEDGES 1600000
#define FDIM_IN 128
#define HID 256
#define NCLS 40

// -------- scratch (no allocation allowed; __device__ globals) --------
__device__ int   g_deg[NNODES];
__device__ float g_inv[NNODES];
__device__ int   g_rowstart[NNODES + 1];
__device__ int   g_cursor[NNODES];
__device__ int   g_csr_src[NEDGES];
__device__ float g_csr_w[NEDGES];
__device__ float g_bufA[(size_t)NNODES * HID];   // aggregation buffer
__device__ float g_bufB[(size_t)NNODES * HID];   // hidden activations
__device__ float g_t4[(size_t)NNODES * NCLS];    // h3 @ W4
__device__ float g_agg4[(size_t)NNODES * NCLS];  // aggregated logits

// -------- degree / normalization / CSR build --------
__global__ void k_zero_deg(int n) {
    int i = blockIdx.x * blockDim.x + threadIdx.x;
    if (i < n) g_deg[i] = 0;
}

__global__ void k_deg(const int* __restrict__ dst, int E) {
    int e = blockIdx.x * blockDim.x + threadIdx.x;
    if (e < E) atomicAdd(&g_deg[dst[e]], 1);
}

__global__ void k_inv(int n) {
    int i = blockIdx.x * blockDim.x + threadIdx.x;
    if (i < n) g_inv[i] = rsqrtf((float)g_deg[i] + 1.0f);
}

// coalesced tiled scan: 49 tiles of 1024, warp-shuffle hierarchy
__global__ void __launch_bounds__(1024)
k_scan(int n) {
    __shared__ int wsum[32];
    int tid = threadIdx.x, lane = tid & 31, wid = tid >> 5;
    int carry = 0;
    int ntiles = (n + 1023) >> 10;
    for (int t = 0; t < ntiles; t++) {
        int i = (t << 10) + tid;
        int v = (i < n) ? g_deg[i] : 0;
        int orig = v;
#pragma unroll
        for (int o = 1; o < 32; o <<= 1) {
            int u = __shfl_up_sync(0xFFFFFFFF, v, o);
            if (lane >= o) v += u;
        }
        if (lane == 31) wsum[wid] = v;
        __syncthreads();
        if (wid == 0) {
            int s = wsum[lane];
#pragma unroll
            for (int o = 1; o < 32; o <<= 1) {
                int u = __shfl_up_sync(0xFFFFFFFF, s, o);
                if (lane >= o) s += u;
            }
            wsum[lane] = s;
        }
        __syncthreads();
        int warpoff = (wid > 0) ? wsum[wid - 1] : 0;
        int excl = carry + warpoff + (v - orig);
        if (i < n) { g_rowstart[i] = excl; g_cursor[i] = excl; }
        int total = wsum[31];
        __syncthreads();
        carry += total;
    }
    if (tid == 0) g_rowstart[n] = carry;
}

__global__ void k_scatter(const int* __restrict__ src, const int* __restrict__ dst, int E) {
    int e = blockIdx.x * blockDim.x + threadIdx.x;
    if (e >= E) return;
    int s = src[e];
    int d = dst[e];
    int pos = atomicAdd(&g_cursor[d], 1);
    g_csr_src[pos] = s;
    g_csr_w[pos]   = g_inv[s] * g_inv[d];
}

// -------- gather-based aggregation: one block per node, thread per column --------
template<int F, int BLK>
__global__ void __launch_bounds__(BLK)
k_gather_agg(const float* __restrict__ h, float* __restrict__ agg) {
    int node = blockIdx.x;
    int f = threadIdx.x;
    if (f >= F) return;
    float iv = g_inv[node];
    float acc = __ldg(h + (size_t)node * F + f) * iv * iv;
    int j   = g_rowstart[node];
    int end = g_rowstart[node + 1];
    for (; j + 4 <= end; j += 4) {
        int   s0 = g_csr_src[j],   s1 = g_csr_src[j+1];
        int   s2 = g_csr_src[j+2], s3 = g_csr_src[j+3];
        float w0 = g_csr_w[j],     w1 = g_csr_w[j+1];
        float w2 = g_csr_w[j+2],   w3 = g_csr_w[j+3];
        float v0 = __ldg(h + (size_t)s0 * F + f);
        float v1 = __ldg(h + (size_t)s1 * F + f);
        float v2 = __ldg(h + (size_t)s2 * F + f);
        float v3 = __ldg(h + (size_t)s3 * F + f);
        acc += w0 * v0;
        acc += w1 * v1;
        acc += w2 * v2;
        acc += w3 * v3;
    }
    for (; j < end; j++) {
        acc += g_csr_w[j] * __ldg(h + (size_t)g_csr_src[j] * F + f);
    }
    agg[(size_t)node * F + f] = acc;
}

// -------- tf32 tensor-core GEMM: C[M,256] = A[M,K] @ B[K,256] (+bias)(+relu) --------
// BM=128, BN=128, BK=16; 8 warps, warp tile 64x32 (2x4 warp grid); m16n8k8 tf32 mma.
__device__ __forceinline__ uint32_t f2tf32(float f) {
    uint32_t u;
    asm("cvt.rna.tf32.f32 %0, %1;" : "=r"(u) : "f"(f));
    return u;
}

__device__ __forceinline__ void mma_tf32(float* c, const uint32_t* a, const uint32_t* b) {
    asm volatile(
        "mma.sync.aligned.m16n8k8.row.col.f32.tf32.tf32.f32 "
        "{%0,%1,%2,%3}, {%4,%5,%6,%7}, {%8,%9}, {%0,%1,%2,%3};"
        : "+f"(c[0]), "+f"(c[1]), "+f"(c[2]), "+f"(c[3])
        : "r"(a[0]), "r"(a[1]), "r"(a[2]), "r"(a[3]), "r"(b[0]), "r"(b[1]));
}

#define AP 20
#define BP 136

__global__ void __launch_bounds__(256)
k_mma_gemm(const float* __restrict__ A, const float* __restrict__ B,
           const float* __restrict__ bias, float* __restrict__ C,
           int M, int K, int relu) {
    __shared__ uint32_t As[128 * AP];
    __shared__ uint32_t Bs[16 * BP];
    int tid = threadIdx.x;
    int bm = blockIdx.y * 128, bn = blockIdx.x * 128;
    int lane = tid & 31, w = tid >> 5;
    int wm = (w & 1) * 64, wn = (w >> 1) * 32;
    int g = lane >> 2, tg = lane & 3;

    float acc[4][4][4];
#pragma unroll
    for (int mt = 0; mt < 4; mt++)
#pragma unroll
        for (int nt = 0; nt < 4; nt++)
#pragma unroll
            for (int i = 0; i < 4; i++) acc[mt][nt][i] = 0.0f;

    // global load coords
    int ar0 = tid >> 2;            // 0..63
    int ac  = (tid & 3) * 4;       // 0,4,8,12
    int br0 = tid >> 5;            // 0..7
    int bc  = (tid & 31) * 4;      // 0..124

    int KT = K >> 4;
    float4 a0v, a1v, b0v, b1v;

    // prefetch tile 0
    {
        int r0 = bm + ar0, r1 = bm + 64 + ar0;
        a0v = (r0 < M) ? *(const float4*)(A + (size_t)r0 * K + ac)
                       : make_float4(0.f, 0.f, 0.f, 0.f);
        a1v = (r1 < M) ? *(const float4*)(A + (size_t)r1 * K + ac)
                       : make_float4(0.f, 0.f, 0.f, 0.f);
        b0v = *(const float4*)(B + (size_t)br0 * 256 + bn + bc);
        b1v = *(const float4*)(B + (size_t)(8 + br0) * 256 + bn + bc);
    }

    for (int kt = 0; kt < KT; kt++) {
        // store prefetched tile (converted to tf32)
        {
            uint4 u;
            u.x = f2tf32(a0v.x); u.y = f2tf32(a0v.y); u.z = f2tf32(a0v.z); u.w = f2tf32(a0v.w);
            *(uint4*)&As[ar0 * AP + ac] = u;
            u.x = f2tf32(a1v.x); u.y = f2tf32(a1v.y); u.z = f2tf32(a1v.z); u.w = f2tf32(a1v.w);
            *(uint4*)&As[(64 + ar0) * AP + ac] = u;
            u.x = f2tf32(b0v.x); u.y = f2tf32(b0v.y); u.z = f2tf32(b0v.z); u.w = f2tf32(b0v.w);
            *(uint4*)&Bs[br0 * BP + bc] = u;
            u.x = f2tf32(b1v.x); u.y = f2tf32(b1v.y); u.z = f2tf32(b1v.z); u.w = f2tf32(b1v.w);
            *(uint4*)&Bs[(8 + br0) * BP + bc] = u;
        }
        __syncthreads();

        // prefetch next tile
        if (kt + 1 < KT) {
            int kofs = (kt + 1) * 16;
            int r0 = bm + ar0, r1 = bm + 64 + ar0;
            a0v = (r0 < M) ? *(const float4*)(A + (size_t)r0 * K + kofs + ac)
                           : make_float4(0.f, 0.f, 0.f, 0.f);
            a1v = (r1 < M) ? *(const float4*)(A + (size_t)r1 * K + kofs + ac)
                           : make_float4(0.f, 0.f, 0.f, 0.f);
            b0v = *(const float4*)(B + (size_t)(kofs + br0) * 256 + bn + bc);
            b1v = *(const float4*)(B + (size_t)(kofs + 8 + br0) * 256 + bn + bc);
        }

        // compute: two k8 steps
#pragma unroll
        for (int kk = 0; kk < 16; kk += 8) {
            uint32_t af[4][4], bf[4][2];
#pragma unroll
            for (int mt = 0; mt < 4; mt++) {
                int r = wm + mt * 16 + g;
                af[mt][0] = As[r * AP + kk + tg];
                af[mt][1] = As[(r + 8) * AP + kk + tg];
                af[mt][2] = As[r * AP + kk + 4 + tg];
                af[mt][3] = As[(r + 8) * AP + kk + 4 + tg];
            }
#pragma unroll
            for (int nt = 0; nt < 4; nt++) {
                int c = wn + nt * 8 + g;
                bf[nt][0] = Bs[(kk + tg) * BP + c];
                bf[nt][1] = Bs[(kk + 4 + tg) * BP + c];
            }
#pragma unroll
            for (int mt = 0; mt < 4; mt++)
#pragma unroll
                for (int nt = 0; nt < 4; nt++)
                    mma_tf32(acc[mt][nt], af[mt], bf[nt]);
        }
        __syncthreads();
    }

    // epilogue: bias (+relu), rows g and g+8, cols 2*tg, 2*tg+1
#pragma unroll
    for (int mt = 0; mt < 4; mt++) {
        int r0 = bm + wm + mt * 16 + g;
#pragma unroll
        for (int nt = 0; nt < 4; nt++) {
            int col = bn + wn + nt * 8 + 2 * tg;
            float bx = bias[col], by = bias[col + 1];
            float2 v0, v1;
            v0.x = acc[mt][nt][0] + bx; v0.y = acc[mt][nt][1] + by;
            v1.x = acc[mt][nt][2] + bx; v1.y = acc[mt][nt][3] + by;
            if (relu) {
                v0.x = fmaxf(v0.x, 0.f); v0.y = fmaxf(v0.y, 0.f);
                v1.x = fmaxf(v1.x, 0.f); v1.y = fmaxf(v1.y, 0.f);
            }
            if (r0 < M)     *(float2*)(C + (size_t)r0 * 256 + col) = v0;
            if (r0 + 8 < M) *(float2*)(C + (size_t)(r0 + 8) * 256 + col) = v1;
        }
    }
}

// -------- GEMM for layer 4: t4[M,40] = A[M,256] @ W4[256,40] (no bias) --------
__global__ void __launch_bounds__(160)
k_gemm40(const float* __restrict__ A, const float* __restrict__ W,
         float* __restrict__ C, int M) {
    __shared__ float Ws[256 * 40];   // 40 KB
    __shared__ float Asm[4 * 256];   // 4 KB
    int tid = threadIdx.x;
    int row0 = blockIdx.x * 4;

    for (int i = tid; i < 256 * 40; i += 160) Ws[i] = W[i];
    for (int i = tid; i < 4 * 256; i += 160) {
        int r = i >> 8;
        if (row0 + r < M) Asm[i] = A[(size_t)(row0 + r) * 256 + (i & 255)];
    }
    __syncthreads();

    int r = tid / 40;
    int c = tid - r * 40;
    if (row0 + r >= M) return;
    float acc = 0.0f;
    const float* a = &Asm[r * 256];
#pragma unroll 8
    for (int k = 0; k < 256; k++) acc += a[k] * Ws[k * 40 + c];
    C[(size_t)(row0 + r) * 40 + c] = acc;
}

// -------- out = log_softmax(agg4 + b4), warp per row (40 cols) --------
__global__ void k_logsoftmax40(const float* __restrict__ b4, float* __restrict__ out, int n) {
    int warp = (blockIdx.x * blockDim.x + threadIdx.x) >> 5;
    int lane = threadIdx.x & 31;
    if (warp >= n) return;
    const float* row = g_agg4 + (size_t)warp * 40;
    float v0 = row[lane] + b4[lane];
    float v1 = (lane < 8) ? row[32 + lane] + b4[32 + lane] : -INFINITY;
    float m = fmaxf(v0, v1);
#pragma unroll
    for (int o = 16; o > 0; o >>= 1) m = fmaxf(m, __shfl_xor_sync(0xFFFFFFFF, m, o));
    float s = __expf(v0 - m) + ((lane < 8) ? __expf(v1 - m) : 0.0f);
#pragma unroll
    for (int o = 16; o > 0; o >>= 1) s += __shfl_xor_sync(0xFFFFFFFF, s, o);
    float l = m + __logf(s);
    out[(size_t)warp * 40 + lane] = v0 - l;
    if (lane < 8) out[(size_t)warp * 40 + 32 + lane] = v1 - l;
}

// ---------------------------------------------------------------
extern "C" void kernel_launch(void* const* d_in, const int* in_sizes, int n_in,
                              void* d_out, int out_size) {
    const float* x  = (const float*)d_in[0];
    const int*   ei = (const int*)d_in[1];
    const float* W1 = (const float*)d_in[2]; const float* b1 = (const float*)d_in[3];
    const float* W2 = (const float*)d_in[4]; const float* b2 = (const float*)d_in[5];
    const float* W3 = (const float*)d_in[6]; const float* b3 = (const float*)d_in[7];
    const float* W4 = (const float*)d_in[8]; const float* b4 = (const float*)d_in[9];
    float* out = (float*)d_out;

    int N = in_sizes[0] / FDIM_IN;
    int E = in_sizes[1] / 2;
    const int* src = ei;
    const int* dst = ei + E;

    void *pA, *pB, *pt4, *pagg4;
    cudaGetSymbolAddress(&pA, g_bufA);
    cudaGetSymbolAddress(&pB, g_bufB);
    cudaGetSymbolAddress(&pt4, g_t4);
    cudaGetSymbolAddress(&pagg4, g_agg4);
    float* bufA = (float*)pA;
    float* bufB = (float*)pB;
    float* t4   = (float*)pt4;
    float* agg4 = (float*)pagg4;

    const int TB = 256;
    // --- degree + norms + CSR (by destination) ---
    k_zero_deg<<<(N + TB - 1) / TB, TB>>>(N);
    k_deg<<<(E + TB - 1) / TB, TB>>>(dst, E);
    k_inv<<<(N + TB - 1) / TB, TB>>>(N);
    k_scan<<<1, 1024>>>(N);
    k_scatter<<<(E + TB - 1) / TB, TB>>>(src, dst, E);

    dim3 gemm_grid(2, (N + 127) / 128);

    // --- Layer 1: aggregate x (128-dim) first, then tf32 GEMM+ReLU ---
    k_gather_agg<FDIM_IN, FDIM_IN><<<N, FDIM_IN>>>(x, bufA);
    k_mma_gemm<<<gemm_grid, 256>>>(bufA, W1, b1, bufB, N, FDIM_IN, 1);

    // --- Layer 2 ---
    k_gather_agg<HID, HID><<<N, HID>>>(bufB, bufA);
    k_mma_gemm<<<gemm_grid, 256>>>(bufA, W2, b2, bufB, N, HID, 1);

    // --- Layer 3 ---
    k_gather_agg<HID, HID><<<N, HID>>>(bufB, bufA);
    k_mma_gemm<<<gemm_grid, 256>>>(bufA, W3, b3, bufB, N, HID, 1);

    // --- Layer 4: GEMM to 40 dims first, then aggregate (40-dim) ---
    k_gemm40<<<(N + 3) / 4, 160>>>(bufB, W4, t4, N);
    k_gather_agg<NCLS, 64><<<N, 64>>>(t4, agg4);

    // --- log_softmax ---
    k_logsoftmax40<<<(N * 32 + TB - 1) / TB, TB>>>(b4, out, N);
}

// round 5
// speedup vs baseline: 2.2110x; 1.3423x over previous
#include <cuda_runtime.h>
#include <cuda_fp16.h>
#include <math.h>
#include <stdint.h>

#define NNODES 50000
#define NEDGES 1600000
#define FDIM_IN 128
#define HID 256
#define NCLS 40
#define SCAN_BLOCKS 49

// -------- scratch (no allocation allowed; __device__ globals) --------
__device__ int     g_deg[NNODES];
__device__ float   g_inv[NNODES];
__device__ int     g_rowstart[NNODES + 1];
__device__ int     g_cursor[NNODES];
__device__ int     g_bsum[SCAN_BLOCKS];
__device__ int     g_boff[SCAN_BLOCKS];
__device__ int     g_csr_src[NEDGES];
__device__ float   g_csr_w[NEDGES];
__device__ float   g_bufA[(size_t)NNODES * HID];    // aggregation out (fp32, GEMM in)
__device__ float   g_bufB[(size_t)NNODES * HID];    // h3 (fp32, gemm40 in)
__device__ __half2 g_h16[(size_t)NNODES * (HID/2)]; // h1/h2 (fp16, gather in)
__device__ __half2 g_x16[(size_t)NNODES * (FDIM_IN/2)];
__device__ __half2 g_t416[(size_t)NNODES * (NCLS/2)];
__device__ float   g_agg4[(size_t)NNODES * NCLS];   // aggregated logits

// -------- degree / normalization --------
__global__ void k_zero_deg(int n) {
    int i = blockIdx.x * blockDim.x + threadIdx.x;
    if (i < n) g_deg[i] = 0;
}

__global__ void k_deg(const int* __restrict__ dst, int E) {
    int e = blockIdx.x * blockDim.x + threadIdx.x;
    if (e < E) atomicAdd(&g_deg[dst[e]], 1);
}

__global__ void k_inv(int n) {
    int i = blockIdx.x * blockDim.x + threadIdx.x;
    if (i < n) g_inv[i] = rsqrtf((float)g_deg[i] + 1.0f);
}

// -------- 3-phase parallel exclusive scan of g_deg --------
__global__ void __launch_bounds__(1024)
k_blocksum(int n) {
    __shared__ int wsum[32];
    int i = blockIdx.x * 1024 + threadIdx.x;
    int lane = threadIdx.x & 31, wid = threadIdx.x >> 5;
    int v = (i < n) ? g_deg[i] : 0;
#pragma unroll
    for (int o = 16; o > 0; o >>= 1) v += __shfl_xor_sync(0xFFFFFFFF, v, o);
    if (lane == 0) wsum[wid] = v;
    __syncthreads();
    if (wid == 0) {
        int s = wsum[lane];
#pragma unroll
        for (int o = 16; o > 0; o >>= 1) s += __shfl_xor_sync(0xFFFFFFFF, s, o);
        if (lane == 0) g_bsum[blockIdx.x] = s;
    }
}

__global__ void k_scanbsums(int n) {
    __shared__ int sm[64];
    int tid = threadIdx.x;
    int v = (tid < SCAN_BLOCKS) ? g_bsum[tid] : 0;
    sm[tid] = v;
    __syncthreads();
    for (int o = 1; o < 64; o <<= 1) {
        int t = (tid >= o) ? sm[tid - o] : 0;
        __syncthreads();
        sm[tid] += t;
        __syncthreads();
    }
    if (tid < SCAN_BLOCKS) g_boff[tid] = sm[tid] - v;  // exclusive
    if (tid == 63) g_rowstart[n] = sm[63];
}

__global__ void __launch_bounds__(1024)
k_scan_apply(int n) {
    __shared__ int wsum[32];
    int i = blockIdx.x * 1024 + threadIdx.x;
    int lane = threadIdx.x & 31, wid = threadIdx.x >> 5;
    int orig = (i < n) ? g_deg[i] : 0;
    int v = orig;
#pragma unroll
    for (int o = 1; o < 32; o <<= 1) {
        int u = __shfl_up_sync(0xFFFFFFFF, v, o);
        if (lane >= o) v += u;
    }
    if (lane == 31) wsum[wid] = v;
    __syncthreads();
    if (wid == 0) {
        int s = wsum[lane];
#pragma unroll
        for (int o = 1; o < 32; o <<= 1) {
            int u = __shfl_up_sync(0xFFFFFFFF, s, o);
            if (lane >= o) s += u;
        }
        wsum[lane] = s;
    }
    __syncthreads();
    int warpoff = (wid > 0) ? wsum[wid - 1] : 0;
    int excl = g_boff[blockIdx.x] + warpoff + (v - orig);
    if (i < n) { g_rowstart[i] = excl; g_cursor[i] = excl; }
}

__global__ void k_scatter(const int* __restrict__ src, const int* __restrict__ dst, int E) {
    int e = blockIdx.x * blockDim.x + threadIdx.x;
    if (e >= E) return;
    int s = src[e];
    int d = dst[e];
    int pos = atomicAdd(&g_cursor[d], 1);
    g_csr_src[pos] = s;
    g_csr_w[pos]   = g_inv[s] * g_inv[d];
}

// -------- fp32 -> fp16 convert (x) --------
__global__ void k_f2h(const float* __restrict__ x, __half2* __restrict__ o, int n2) {
    int i = blockIdx.x * blockDim.x + threadIdx.x;
    if (i >= n2) return;
    float2 v = ((const float2*)x)[i];
    o[i] = __float22half2_rn(v);
}

// -------- gather aggregation: block per node, thread per half2 column pair --------
// agg[n,:] = h[n,:]*inv^2 + sum_j w_j * h[src_j,:]   (h fp16, acc fp32)
template<int F2, int BLK>
__global__ void __launch_bounds__(BLK)
k_gather_agg_h(const __half2* __restrict__ h, float* __restrict__ agg) {
    int node = blockIdx.x;
    int f = threadIdx.x;
    if (f >= F2) return;
    float iv = g_inv[node]; float iv2 = iv * iv;
    float2 sv = __half22float2(h[(size_t)node * F2 + f]);
    float ax = sv.x * iv2, ay = sv.y * iv2;
    int j   = g_rowstart[node];
    int end = g_rowstart[node + 1];
    for (; j + 4 <= end; j += 4) {
        int   s0 = g_csr_src[j],   s1 = g_csr_src[j+1];
        int   s2 = g_csr_src[j+2], s3 = g_csr_src[j+3];
        float w0 = g_csr_w[j],     w1 = g_csr_w[j+1];
        float w2 = g_csr_w[j+2],   w3 = g_csr_w[j+3];
        float2 v0 = __half22float2(__ldg(h + (size_t)s0 * F2 + f));
        float2 v1 = __half22float2(__ldg(h + (size_t)s1 * F2 + f));
        float2 v2 = __half22float2(__ldg(h + (size_t)s2 * F2 + f));
        float2 v3 = __half22float2(__ldg(h + (size_t)s3 * F2 + f));
        ax += w0 * v0.x; ay += w0 * v0.y;
        ax += w1 * v1.x; ay += w1 * v1.y;
        ax += w2 * v2.x; ay += w2 * v2.y;
        ax += w3 * v3.x; ay += w3 * v3.y;
    }
    for (; j < end; j++) {
        float w = g_csr_w[j];
        float2 v = __half22float2(__ldg(h + (size_t)g_csr_src[j] * F2 + f));
        ax += w * v.x; ay += w * v.y;
    }
    float2 o = make_float2(ax, ay);
    *(float2*)(agg + (size_t)node * (2 * F2) + 2 * f) = o;
}

// warp-per-node variant for narrow F (F2 <= 32); 8 warps per block
template<int F2>
__global__ void __launch_bounds__(256)
k_gather_agg_w(const __half2* __restrict__ h, float* __restrict__ agg, int n) {
    int node = blockIdx.x * 8 + (threadIdx.x >> 5);
    int f = threadIdx.x & 31;
    if (node >= n || f >= F2) return;
    float iv = g_inv[node]; float iv2 = iv * iv;
    float2 sv = __half22float2(h[(size_t)node * F2 + f]);
    float ax = sv.x * iv2, ay = sv.y * iv2;
    int j   = g_rowstart[node];
    int end = g_rowstart[node + 1];
    for (; j + 4 <= end; j += 4) {
        int   s0 = g_csr_src[j],   s1 = g_csr_src[j+1];
        int   s2 = g_csr_src[j+2], s3 = g_csr_src[j+3];
        float w0 = g_csr_w[j],     w1 = g_csr_w[j+1];
        float w2 = g_csr_w[j+2],   w3 = g_csr_w[j+3];
        float2 v0 = __half22float2(__ldg(h + (size_t)s0 * F2 + f));
        float2 v1 = __half22float2(__ldg(h + (size_t)s1 * F2 + f));
        float2 v2 = __half22float2(__ldg(h + (size_t)s2 * F2 + f));
        float2 v3 = __half22float2(__ldg(h + (size_t)s3 * F2 + f));
        ax += w0 * v0.x; ay += w0 * v0.y;
        ax += w1 * v1.x; ay += w1 * v1.y;
        ax += w2 * v2.x; ay += w2 * v2.y;
        ax += w3 * v3.x; ay += w3 * v3.y;
    }
    for (; j < end; j++) {
        float w = g_csr_w[j];
        float2 v = __half22float2(__ldg(h + (size_t)g_csr_src[j] * F2 + f));
        ax += w * v.x; ay += w * v.y;
    }
    float2 o = make_float2(ax, ay);
    *(float2*)(agg + (size_t)node * (2 * F2) + 2 * f) = o;
}

// -------- tf32 tensor-core GEMM: C[M,256] = A[M,K] @ B[K,256] (+bias, relu) --------
__device__ __forceinline__ uint32_t f2tf32(float f) {
    uint32_t u;
    asm("cvt.rna.tf32.f32 %0, %1;" : "=r"(u) : "f"(f));
    return u;
}

__device__ __forceinline__ void mma_tf32(float* c, const uint32_t* a, const uint32_t* b) {
    asm volatile(
        "mma.sync.aligned.m16n8k8.row.col.f32.tf32.tf32.f32 "
        "{%0,%1,%2,%3}, {%4,%5,%6,%7}, {%8,%9}, {%0,%1,%2,%3};"
        : "+f"(c[0]), "+f"(c[1]), "+f"(c[2]), "+f"(c[3])
        : "r"(a[0]), "r"(a[1]), "r"(a[2]), "r"(a[3]), "r"(b[0]), "r"(b[1]));
}

#define AP 20
#define BP 136

// out_mode: 0 -> fp32 C32, 1 -> fp16 C16 (half2 stores)
__global__ void __launch_bounds__(256)
k_mma_gemm(const float* __restrict__ A, const float* __restrict__ B,
           const float* __restrict__ bias, float* __restrict__ C32,
           __half2* __restrict__ C16, int M, int K, int relu, int out_mode) {
    __shared__ uint32_t As[128 * AP];
    __shared__ uint32_t Bs[16 * BP];
    int tid = threadIdx.x;
    int bm = blockIdx.y * 128, bn = blockIdx.x * 128;
    int lane = tid & 31, w = tid >> 5;
    int wm = (w & 1) * 64, wn = (w >> 1) * 32;
    int g = lane >> 2, tg = lane & 3;

    float acc[4][4][4];
#pragma unroll
    for (int mt = 0; mt < 4; mt++)
#pragma unroll
        for (int nt = 0; nt < 4; nt++)
#pragma unroll
            for (int i = 0; i < 4; i++) acc[mt][nt][i] = 0.0f;

    int ar0 = tid >> 2;
    int ac  = (tid & 3) * 4;
    int br0 = tid >> 5;
    int bc  = (tid & 31) * 4;

    int KT = K >> 4;
    float4 a0v, a1v, b0v, b1v;

    {
        int r0 = bm + ar0, r1 = bm + 64 + ar0;
        a0v = (r0 < M) ? *(const float4*)(A + (size_t)r0 * K + ac)
                       : make_float4(0.f, 0.f, 0.f, 0.f);
        a1v = (r1 < M) ? *(const float4*)(A + (size_t)r1 * K + ac)
                       : make_float4(0.f, 0.f, 0.f, 0.f);
        b0v = *(const float4*)(B + (size_t)br0 * 256 + bn + bc);
        b1v = *(const float4*)(B + (size_t)(8 + br0) * 256 + bn + bc);
    }

    for (int kt = 0; kt < KT; kt++) {
        {
            uint4 u;
            u.x = f2tf32(a0v.x); u.y = f2tf32(a0v.y); u.z = f2tf32(a0v.z); u.w = f2tf32(a0v.w);
            *(uint4*)&As[ar0 * AP + ac] = u;
            u.x = f2tf32(a1v.x); u.y = f2tf32(a1v.y); u.z = f2tf32(a1v.z); u.w = f2tf32(a1v.w);
            *(uint4*)&As[(64 + ar0) * AP + ac] = u;
            u.x = f2tf32(b0v.x); u.y = f2tf32(b0v.y); u.z = f2tf32(b0v.z); u.w = f2tf32(b0v.w);
            *(uint4*)&Bs[br0 * BP + bc] = u;
            u.x = f2tf32(b1v.x); u.y = f2tf32(b1v.y); u.z = f2tf32(b1v.z); u.w = f2tf32(b1v.w);
            *(uint4*)&Bs[(8 + br0) * BP + bc] = u;
        }
        __syncthreads();

        if (kt + 1 < KT) {
            int kofs = (kt + 1) * 16;
            int r0 = bm + ar0, r1 = bm + 64 + ar0;
            a0v = (r0 < M) ? *(const float4*)(A + (size_t)r0 * K + kofs + ac)
                           : make_float4(0.f, 0.f, 0.f, 0.f);
            a1v = (r1 < M) ? *(const float4*)(A + (size_t)r1 * K + kofs + ac)
                           : make_float4(0.f, 0.f, 0.f, 0.f);
            b0v = *(const float4*)(B + (size_t)(kofs + br0) * 256 + bn + bc);
            b1v = *(const float4*)(B + (size_t)(kofs + 8 + br0) * 256 + bn + bc);
        }

#pragma unroll
        for (int kk = 0; kk < 16; kk += 8) {
            uint32_t af[4][4], bf[4][2];
#pragma unroll
            for (int mt = 0; mt < 4; mt++) {
                int r = wm + mt * 16 + g;
                af[mt][0] = As[r * AP + kk + tg];
                af[mt][1] = As[(r + 8) * AP + kk + tg];
                af[mt][2] = As[r * AP + kk + 4 + tg];
                af[mt][3] = As[(r + 8) * AP + kk + 4 + tg];
            }
#pragma unroll
            for (int nt = 0; nt < 4; nt++) {
                int c = wn + nt * 8 + g;
                bf[nt][0] = Bs[(kk + tg) * BP + c];
                bf[nt][1] = Bs[(kk + 4 + tg) * BP + c];
            }
#pragma unroll
            for (int mt = 0; mt < 4; mt++)
#pragma unroll
                for (int nt = 0; nt < 4; nt++)
                    mma_tf32(acc[mt][nt], af[mt], bf[nt]);
        }
        __syncthreads();
    }

#pragma unroll
    for (int mt = 0; mt < 4; mt++) {
        int r0 = bm + wm + mt * 16 + g;
#pragma unroll
        for (int nt = 0; nt < 4; nt++) {
            int col = bn + wn + nt * 8 + 2 * tg;
            float bx = bias[col], by = bias[col + 1];
            float2 v0, v1;
            v0.x = acc[mt][nt][0] + bx; v0.y = acc[mt][nt][1] + by;
            v1.x = acc[mt][nt][2] + bx; v1.y = acc[mt][nt][3] + by;
            if (relu) {
                v0.x = fmaxf(v0.x, 0.f); v0.y = fmaxf(v0.y, 0.f);
                v1.x = fmaxf(v1.x, 0.f); v1.y = fmaxf(v1.y, 0.f);
            }
            if (out_mode == 0) {
                if (r0 < M)     *(float2*)(C32 + (size_t)r0 * 256 + col) = v0;
                if (r0 + 8 < M) *(float2*)(C32 + (size_t)(r0 + 8) * 256 + col) = v1;
            } else {
                if (r0 < M)     C16[((size_t)r0 * 256 + col) >> 1] = __float22half2_rn(v0);
                if (r0 + 8 < M) C16[((size_t)(r0 + 8) * 256 + col) >> 1] = __float22half2_rn(v1);
            }
        }
    }
}

// -------- layer 4 GEMM: t4[M,40] = A[M,256] @ W4[256,40], fp16 out --------
__global__ void __launch_bounds__(160)
k_gemm40(const float* __restrict__ A, const float* __restrict__ W,
         __half* __restrict__ C16, int M) {
    __shared__ float Ws[256 * 40];
    __shared__ float Asm[4 * 256];
    int tid = threadIdx.x;
    int row0 = blockIdx.x * 4;

    for (int i = tid; i < 256 * 40; i += 160) Ws[i] = W[i];
    for (int i = tid; i < 4 * 256; i += 160) {
        int r = i >> 8;
        if (row0 + r < M) Asm[i] = A[(size_t)(row0 + r) * 256 + (i & 255)];
    }
    __syncthreads();

    int r = tid / 40;
    int c = tid - r * 40;
    if (row0 + r >= M) return;
    float acc = 0.0f;
    const float* a = &Asm[r * 256];
#pragma unroll 8
    for (int k = 0; k < 256; k++) acc += a[k] * Ws[k * 40 + c];
    C16[(size_t)(row0 + r) * 40 + c] = __float2half_rn(acc);
}

// -------- out = log_softmax(agg4 + b4), warp per row (40 cols) --------
__global__ void k_logsoftmax40(const float* __restrict__ b4, float* __restrict__ out, int n) {
    int warp = (blockIdx.x * blockDim.x + threadIdx.x) >> 5;
    int lane = threadIdx.x & 31;
    if (warp >= n) return;
    const float* row = g_agg4 + (size_t)warp * 40;
    float v0 = row[lane] + b4[lane];
    float v1 = (lane < 8) ? row[32 + lane] + b4[32 + lane] : -INFINITY;
    float m = fmaxf(v0, v1);
#pragma unroll
    for (int o = 16; o > 0; o >>= 1) m = fmaxf(m, __shfl_xor_sync(0xFFFFFFFF, m, o));
    float s = __expf(v0 - m) + ((lane < 8) ? __expf(v1 - m) : 0.0f);
#pragma unroll
    for (int o = 16; o > 0; o >>= 1) s += __shfl_xor_sync(0xFFFFFFFF, s, o);
    float l = m + __logf(s);
    out[(size_t)warp * 40 + lane] = v0 - l;
    if (lane < 8) out[(size_t)warp * 40 + 32 + lane] = v1 - l;
}

// ---------------------------------------------------------------
extern "C" void kernel_launch(void* const* d_in, const int* in_sizes, int n_in,
                              void* d_out, int out_size) {
    const float* x  = (const float*)d_in[0];
    const int*   ei = (const int*)d_in[1];
    const float* W1 = (const float*)d_in[2]; const float* b1 = (const float*)d_in[3];
    const float* W2 = (const float*)d_in[4]; const float* b2 = (const float*)d_in[5];
    const float* W3 = (const float*)d_in[6]; const float* b3 = (const float*)d_in[7];
    const float* W4 = (const float*)d_in[8]; const float* b4 = (const float*)d_in[9];
    float* out = (float*)d_out;

    int N = in_sizes[0] / FDIM_IN;
    int E = in_sizes[1] / 2;
    const int* src = ei;
    const int* dst = ei + E;

    void *pA, *pB, *ph16, *px16, *pt416, *pagg4;
    cudaGetSymbolAddress(&pA, g_bufA);
    cudaGetSymbolAddress(&pB, g_bufB);
    cudaGetSymbolAddress(&ph16, g_h16);
    cudaGetSymbolAddress(&px16, g_x16);
    cudaGetSymbolAddress(&pt416, g_t416);
    cudaGetSymbolAddress(&pagg4, g_agg4);
    float*   bufA = (float*)pA;
    float*   bufB = (float*)pB;
    __half2* h16  = (__half2*)ph16;
    __half2* x16  = (__half2*)px16;
    __half2* t416 = (__half2*)pt416;
    float*   agg4 = (float*)pagg4;

    const int TB = 256;
    // --- degree + norms + CSR (by destination) ---
    k_zero_deg<<<(N + TB - 1) / TB, TB>>>(N);
    k_deg<<<(E + TB - 1) / TB, TB>>>(dst, E);
    k_inv<<<(N + TB - 1) / TB, TB>>>(N);
    k_blocksum<<<SCAN_BLOCKS, 1024>>>(N);
    k_scanbsums<<<1, 64>>>(N);
    k_scan_apply<<<SCAN_BLOCKS, 1024>>>(N);
    k_scatter<<<(E + TB - 1) / TB, TB>>>(src, dst, E);

    // x -> fp16
    k_f2h<<<(N * 64 + TB - 1) / TB, TB>>>(x, x16, N * 64);

    dim3 gemm_grid(2, (N + 127) / 128);

    // --- Layer 1: aggregate x16 (128-dim), tf32 GEMM+ReLU -> h1 (fp16) ---
    k_gather_agg_h<64, 64><<<N, 64>>>(x16, bufA);
    k_mma_gemm<<<gemm_grid, 256>>>(bufA, W1, b1, nullptr, h16, N, FDIM_IN, 1, 1);

    // --- Layer 2 ---
    k_gather_agg_h<128, 128><<<N, 128>>>(h16, bufA);
    k_mma_gemm<<<gemm_grid, 256>>>(bufA, W2, b2, nullptr, h16, N, HID, 1, 1);

    // --- Layer 3: output fp32 h3 (consumed by gemm40) ---
    k_gather_agg_h<128, 128><<<N, 128>>>(h16, bufA);
    k_mma_gemm<<<gemm_grid, 256>>>(bufA, W3, b3, bufB, nullptr, N, HID, 1, 0);

    // --- Layer 4: GEMM to 40 dims (fp16), aggregate, log_softmax ---
    k_gemm40<<<(N + 3) / 4, 160>>>(bufB, W4, (__half*)t416, N);
    k_gather_agg_w<20><<<(N + 7) / 8, 256>>>(t416, agg4, N);
    k_logsoftmax40<<<(N * 32 + TB - 1) / TB, TB>>>(b4, out, N);
}

// round 6
// speedup vs baseline: 2.4338x; 1.1007x over previous
#include <cuda_runtime.h>
#include <cuda_fp16.h>
#include <math.h>
#include <stdint.h>

#define NNODES 50000
#define NEDGES 1600000
#define FDIM_IN 128
#define HID 256
#define NCLS 40
#define SCAN_BLOCKS 49

// -------- scratch (no allocation allowed; __device__ globals) --------
__device__ int     g_deg[NNODES];
__device__ float   g_inv[NNODES];
__device__ int     g_rowstart[NNODES + 1];
__device__ int     g_cursor[NNODES];
__device__ int     g_bsum[SCAN_BLOCKS];
__device__ int     g_boff[SCAN_BLOCKS];
__device__ int     g_csr_src[NEDGES];
__device__ float   g_csr_w[NEDGES];
__device__ __half2 g_aggh[(size_t)NNODES * (HID/2)];   // aggregation out (fp16, GEMM A)
__device__ __half2 g_h16[(size_t)NNODES * (HID/2)];    // GEMM out (fp16, gather in)
__device__ __half2 g_x16[(size_t)NNODES * (FDIM_IN/2)];
__device__ __half2 g_t416[(size_t)NNODES * (NCLS/2)];
__device__ float   g_agg4[(size_t)NNODES * NCLS];      // aggregated logits
__device__ __half  g_wt1[256 * 128];                   // W1^T fp16 [n][k]
__device__ __half  g_wt2[256 * 256];
__device__ __half  g_wt3[256 * 256];

// -------- degree / normalization --------
__global__ void k_zero_deg(int n) {
    int i = blockIdx.x * blockDim.x + threadIdx.x;
    if (i < n) g_deg[i] = 0;
}

__global__ void k_deg(const int* __restrict__ dst, int E) {
    int e = blockIdx.x * blockDim.x + threadIdx.x;
    if (e < E) atomicAdd(&g_deg[dst[e]], 1);
}

__global__ void k_inv(int n) {
    int i = blockIdx.x * blockDim.x + threadIdx.x;
    if (i < n) g_inv[i] = rsqrtf((float)g_deg[i] + 1.0f);
}

// -------- 3-phase parallel exclusive scan of g_deg --------
__global__ void __launch_bounds__(1024)
k_blocksum(int n) {
    __shared__ int wsum[32];
    int i = blockIdx.x * 1024 + threadIdx.x;
    int lane = threadIdx.x & 31, wid = threadIdx.x >> 5;
    int v = (i < n) ? g_deg[i] : 0;
#pragma unroll
    for (int o = 16; o > 0; o >>= 1) v += __shfl_xor_sync(0xFFFFFFFF, v, o);
    if (lane == 0) wsum[wid] = v;
    __syncthreads();
    if (wid == 0) {
        int s = wsum[lane];
#pragma unroll
        for (int o = 16; o > 0; o >>= 1) s += __shfl_xor_sync(0xFFFFFFFF, s, o);
        if (lane == 0) g_bsum[blockIdx.x] = s;
    }
}

__global__ void k_scanbsums(int n) {
    __shared__ int sm[64];
    int tid = threadIdx.x;
    int v = (tid < SCAN_BLOCKS) ? g_bsum[tid] : 0;
    sm[tid] = v;
    __syncthreads();
    for (int o = 1; o < 64; o <<= 1) {
        int t = (tid >= o) ? sm[tid - o] : 0;
        __syncthreads();
        sm[tid] += t;
        __syncthreads();
    }
    if (tid < SCAN_BLOCKS) g_boff[tid] = sm[tid] - v;  // exclusive
    if (tid == 63) g_rowstart[n] = sm[63];
}

__global__ void __launch_bounds__(1024)
k_scan_apply(int n) {
    __shared__ int wsum[32];
    int i = blockIdx.x * 1024 + threadIdx.x;
    int lane = threadIdx.x & 31, wid = threadIdx.x >> 5;
    int orig = (i < n) ? g_deg[i] : 0;
    int v = orig;
#pragma unroll
    for (int o = 1; o < 32; o <<= 1) {
        int u = __shfl_up_sync(0xFFFFFFFF, v, o);
        if (lane >= o) v += u;
    }
    if (lane == 31) wsum[wid] = v;
    __syncthreads();
    if (wid == 0) {
        int s = wsum[lane];
#pragma unroll
        for (int o = 1; o < 32; o <<= 1) {
            int u = __shfl_up_sync(0xFFFFFFFF, s, o);
            if (lane >= o) s += u;
        }
        wsum[lane] = s;
    }
    __syncthreads();
    int warpoff = (wid > 0) ? wsum[wid - 1] : 0;
    int excl = g_boff[blockIdx.x] + warpoff + (v - orig);
    if (i < n) { g_rowstart[i] = excl; g_cursor[i] = excl; }
}

__global__ void k_scatter(const int* __restrict__ src, const int* __restrict__ dst, int E) {
    int e = blockIdx.x * blockDim.x + threadIdx.x;
    if (e >= E) return;
    int s = src[e];
    int d = dst[e];
    int pos = atomicAdd(&g_cursor[d], 1);
    g_csr_src[pos] = s;
    g_csr_w[pos]   = g_inv[s] * g_inv[d];
}

// -------- fp32 -> fp16 convert (x) --------
__global__ void k_f2h(const float* __restrict__ x, __half2* __restrict__ o, int n2) {
    int i = blockIdx.x * blockDim.x + threadIdx.x;
    if (i >= n2) return;
    float2 v = ((const float2*)x)[i];
    o[i] = __float22half2_rn(v);
}

// -------- weight transpose + fp16 convert: Wt[n][k] = (half)W[k][n] --------
__global__ void k_wt(const float* __restrict__ W, __half* __restrict__ Wt, int K, int Nc) {
    __shared__ float t[32][33];
    int k0 = blockIdx.x * 32, n0 = blockIdx.y * 32;
    int tx = threadIdx.x, ty = threadIdx.y;  // 32 x 8
    for (int i = ty; i < 32; i += 8)
        t[i][tx] = W[(size_t)(k0 + i) * Nc + n0 + tx];
    __syncthreads();
    for (int i = ty; i < 32; i += 8)
        Wt[(size_t)(n0 + i) * K + k0 + tx] = __float2half_rn(t[tx][i]);
}

// -------- gather aggregation: block per node, thread per half2 column pair --------
// agg[n,:] = h[n,:]*inv^2 + sum_j w_j * h[src_j,:]   (h fp16, acc fp32, out fp16)
template<int F2, int BLK>
__global__ void __launch_bounds__(BLK)
k_gather_agg_h(const __half2* __restrict__ h, __half2* __restrict__ agg) {
    int node = blockIdx.x;
    int f = threadIdx.x;
    if (f >= F2) return;
    float iv = g_inv[node]; float iv2 = iv * iv;
    float2 sv = __half22float2(h[(size_t)node * F2 + f]);
    float ax = sv.x * iv2, ay = sv.y * iv2;
    int j   = g_rowstart[node];
    int end = g_rowstart[node + 1];
    for (; j + 4 <= end; j += 4) {
        int   s0 = g_csr_src[j],   s1 = g_csr_src[j+1];
        int   s2 = g_csr_src[j+2], s3 = g_csr_src[j+3];
        float w0 = g_csr_w[j],     w1 = g_csr_w[j+1];
        float w2 = g_csr_w[j+2],   w3 = g_csr_w[j+3];
        float2 v0 = __half22float2(__ldg(h + (size_t)s0 * F2 + f));
        float2 v1 = __half22float2(__ldg(h + (size_t)s1 * F2 + f));
        float2 v2 = __half22float2(__ldg(h + (size_t)s2 * F2 + f));
        float2 v3 = __half22float2(__ldg(h + (size_t)s3 * F2 + f));
        ax += w0 * v0.x; ay += w0 * v0.y;
        ax += w1 * v1.x; ay += w1 * v1.y;
        ax += w2 * v2.x; ay += w2 * v2.y;
        ax += w3 * v3.x; ay += w3 * v3.y;
    }
    for (; j < end; j++) {
        float w = g_csr_w[j];
        float2 v = __half22float2(__ldg(h + (size_t)g_csr_src[j] * F2 + f));
        ax += w * v.x; ay += w * v.y;
    }
    agg[(size_t)node * F2 + f] = __float22half2_rn(make_float2(ax, ay));
}

// warp-per-node variant for narrow F (F2 <= 32); fp32 out for softmax
template<int F2>
__global__ void __launch_bounds__(256)
k_gather_agg_w(const __half2* __restrict__ h, float* __restrict__ agg, int n) {
    int node = blockIdx.x * 8 + (threadIdx.x >> 5);
    int f = threadIdx.x & 31;
    if (node >= n || f >= F2) return;
    float iv = g_inv[node]; float iv2 = iv * iv;
    float2 sv = __half22float2(h[(size_t)node * F2 + f]);
    float ax = sv.x * iv2, ay = sv.y * iv2;
    int j   = g_rowstart[node];
    int end = g_rowstart[node + 1];
    for (; j + 4 <= end; j += 4) {
        int   s0 = g_csr_src[j],   s1 = g_csr_src[j+1];
        int   s2 = g_csr_src[j+2], s3 = g_csr_src[j+3];
        float w0 = g_csr_w[j],     w1 = g_csr_w[j+1];
        float w2 = g_csr_w[j+2],   w3 = g_csr_w[j+3];
        float2 v0 = __half22float2(__ldg(h + (size_t)s0 * F2 + f));
        float2 v1 = __half22float2(__ldg(h + (size_t)s1 * F2 + f));
        float2 v2 = __half22float2(__ldg(h + (size_t)s2 * F2 + f));
        float2 v3 = __half22float2(__ldg(h + (size_t)s3 * F2 + f));
        ax += w0 * v0.x; ay += w0 * v0.y;
        ax += w1 * v1.x; ay += w1 * v1.y;
        ax += w2 * v2.x; ay += w2 * v2.y;
        ax += w3 * v3.x; ay += w3 * v3.y;
    }
    for (; j < end; j++) {
        float w = g_csr_w[j];
        float2 v = __half22float2(__ldg(h + (size_t)g_csr_src[j] * F2 + f));
        ax += w * v.x; ay += w * v.y;
    }
    float2 o = make_float2(ax, ay);
    *(float2*)(agg + (size_t)node * (2 * F2) + 2 * f) = o;
}

// -------- fp16 tensor-core GEMM: C[M,256] = A[M,K] @ Wt[256,K]^T (+bias, relu) --------
// BM=128, BN=128, BK=32; 8 warps, warp tile 64x32; m16n8k16 fp16 mma, fp32 accum.
// A: [M][K] halves row-major; Wt: [256][K] halves (k-contiguous).
__device__ __forceinline__ void mma_f16(float* c, const uint32_t* a, const uint32_t* b) {
    asm volatile(
        "mma.sync.aligned.m16n8k16.row.col.f32.f16.f16.f32 "
        "{%0,%1,%2,%3}, {%4,%5,%6,%7}, {%8,%9}, {%0,%1,%2,%3};"
        : "+f"(c[0]), "+f"(c[1]), "+f"(c[2]), "+f"(c[3])
        : "r"(a[0]), "r"(a[1]), "r"(a[2]), "r"(a[3]), "r"(b[0]), "r"(b[1]));
}

#define HPAD 40   // halves per smem row (32 data + 8 pad) -> conflict-free frag loads

__global__ void __launch_bounds__(256)
k_hgemm(const __half* __restrict__ A, const __half* __restrict__ Bt,
        const float* __restrict__ bias, __half2* __restrict__ C16,
        int M, int K, int relu) {
    __shared__ __half As[128 * HPAD];
    __shared__ __half Bs[128 * HPAD];
    int tid = threadIdx.x;
    int bm = blockIdx.y * 128, bn = blockIdx.x * 128;
    int lane = tid & 31, w = tid >> 5;
    int wm = (w & 1) * 64, wn = (w >> 1) * 32;
    int g = lane >> 2, tg = lane & 3;

    float acc[4][4][4];
#pragma unroll
    for (int mt = 0; mt < 4; mt++)
#pragma unroll
        for (int nt = 0; nt < 4; nt++)
#pragma unroll
            for (int i = 0; i < 4; i++) acc[mt][nt][i] = 0.0f;

    // global loads: per tile, each operand = 128 rows x 32 halves = 512 x 16B chunks;
    // 2 chunks per thread per operand.
    int row0 = tid >> 2;          // 0..63
    int cc   = (tid & 3) * 8;     // half offset 0,8,16,24

    int KT = K >> 5;
    uint4 apf[2], bpf[2], zero4 = make_uint4(0, 0, 0, 0);

    // prefetch tile 0
#pragma unroll
    for (int i = 0; i < 2; i++) {
        int r = row0 + i * 64;
        apf[i] = (bm + r < M) ? *(const uint4*)(A + (size_t)(bm + r) * K + cc) : zero4;
        bpf[i] = *(const uint4*)(Bt + (size_t)(bn + r) * K + cc);
    }

    for (int kt = 0; kt < KT; kt++) {
#pragma unroll
        for (int i = 0; i < 2; i++) {
            int r = row0 + i * 64;
            *(uint4*)&As[r * HPAD + cc] = apf[i];
            *(uint4*)&Bs[r * HPAD + cc] = bpf[i];
        }
        __syncthreads();

        if (kt + 1 < KT) {
            int kofs = (kt + 1) * 32;
#pragma unroll
            for (int i = 0; i < 2; i++) {
                int r = row0 + i * 64;
                apf[i] = (bm + r < M) ? *(const uint4*)(A + (size_t)(bm + r) * K + kofs + cc) : zero4;
                bpf[i] = *(const uint4*)(Bt + (size_t)(bn + r) * K + kofs + cc);
            }
        }

#pragma unroll
        for (int kk = 0; kk < 32; kk += 16) {
            uint32_t af[4][4], bf[4][2];
#pragma unroll
            for (int mt = 0; mt < 4; mt++) {
                int base = (wm + mt * 16 + g) * HPAD + kk + 2 * tg;
                af[mt][0] = *(const uint32_t*)&As[base];
                af[mt][1] = *(const uint32_t*)&As[base + 8 * HPAD];
                af[mt][2] = *(const uint32_t*)&As[base + 8];
                af[mt][3] = *(const uint32_t*)&As[base + 8 * HPAD + 8];
            }
#pragma unroll
            for (int nt = 0; nt < 4; nt++) {
                int base = (wn + nt * 8 + g) * HPAD + kk + 2 * tg;
                bf[nt][0] = *(const uint32_t*)&Bs[base];
                bf[nt][1] = *(const uint32_t*)&Bs[base + 8];
            }
#pragma unroll
            for (int mt = 0; mt < 4; mt++)
#pragma unroll
                for (int nt = 0; nt < 4; nt++)
                    mma_f16(acc[mt][nt], af[mt], bf[nt]);
        }
        __syncthreads();
    }

    // epilogue: bias (+relu), fp16 out
#pragma unroll
    for (int mt = 0; mt < 4; mt++) {
        int r0 = bm + wm + mt * 16 + g;
#pragma unroll
        for (int nt = 0; nt < 4; nt++) {
            int col = bn + wn + nt * 8 + 2 * tg;
            float bx = bias[col], by = bias[col + 1];
            float2 v0, v1;
            v0.x = acc[mt][nt][0] + bx; v0.y = acc[mt][nt][1] + by;
            v1.x = acc[mt][nt][2] + bx; v1.y = acc[mt][nt][3] + by;
            if (relu) {
                v0.x = fmaxf(v0.x, 0.f); v0.y = fmaxf(v0.y, 0.f);
                v1.x = fmaxf(v1.x, 0.f); v1.y = fmaxf(v1.y, 0.f);
            }
            if (r0 < M)     C16[((size_t)r0 * 256 + col) >> 1] = __float22half2_rn(v0);
            if (r0 + 8 < M) C16[((size_t)(r0 + 8) * 256 + col) >> 1] = __float22half2_rn(v1);
        }
    }
}

// -------- layer 4 GEMM: t4[M,40] = A16[M,256] @ W4[256,40], fp16 out --------
__global__ void __launch_bounds__(160)
k_gemm40(const __half* __restrict__ A16, const float* __restrict__ W,
         __half* __restrict__ C16, int M) {
    __shared__ float Ws[256 * 40];
    __shared__ float Asm[4 * 256];
    int tid = threadIdx.x;
    int row0 = blockIdx.x * 4;

    for (int i = tid; i < 256 * 40; i += 160) Ws[i] = W[i];
    for (int i = tid; i < 4 * 256; i += 160) {
        int r = i >> 8;
        if (row0 + r < M) Asm[i] = __half2float(A16[(size_t)(row0 + r) * 256 + (i & 255)]);
    }
    __syncthreads();

    int r = tid / 40;
    int c = tid - r * 40;
    if (row0 + r >= M) return;
    float acc = 0.0f;
    const float* a = &Asm[r * 256];
#pragma unroll 8
    for (int k = 0; k < 256; k++) acc += a[k] * Ws[k * 40 + c];
    C16[(size_t)(row0 + r) * 40 + c] = __float2half_rn(acc);
}

// -------- out = log_softmax(agg4 + b4), warp per row (40 cols) --------
__global__ void k_logsoftmax40(const float* __restrict__ b4, float* __restrict__ out, int n) {
    int warp = (blockIdx.x * blockDim.x + threadIdx.x) >> 5;
    int lane = threadIdx.x & 31;
    if (warp >= n) return;
    const float* row = g_agg4 + (size_t)warp * 40;
    float v0 = row[lane] + b4[lane];
    float v1 = (lane < 8) ? row[32 + lane] + b4[32 + lane] : -INFINITY;
    float m = fmaxf(v0, v1);
#pragma unroll
    for (int o = 16; o > 0; o >>= 1) m = fmaxf(m, __shfl_xor_sync(0xFFFFFFFF, m, o));
    float s = __expf(v0 - m) + ((lane < 8) ? __expf(v1 - m) : 0.0f);
#pragma unroll
    for (int o = 16; o > 0; o >>= 1) s += __shfl_xor_sync(0xFFFFFFFF, s, o);
    float l = m + __logf(s);
    out[(size_t)warp * 40 + lane] = v0 - l;
    if (lane < 8) out[(size_t)warp * 40 + 32 + lane] = v1 - l;
}

// ---------------------------------------------------------------
extern "C" void kernel_launch(void* const* d_in, const int* in_sizes, int n_in,
                              void* d_out, int out_size) {
    const float* x  = (const float*)d_in[0];
    const int*   ei = (const int*)d_in[1];
    const float* W1 = (const float*)d_in[2]; const float* b1 = (const float*)d_in[3];
    const float* W2 = (const float*)d_in[4]; const float* b2 = (const float*)d_in[5];
    const float* W3 = (const float*)d_in[6]; const float* b3 = (const float*)d_in[7];
    const float* W4 = (const float*)d_in[8]; const float* b4 = (const float*)d_in[9];
    float* out = (float*)d_out;

    int N = in_sizes[0] / FDIM_IN;
    int E = in_sizes[1] / 2;
    const int* src = ei;
    const int* dst = ei + E;

    void *paggh, *ph16, *px16, *pt416, *pagg4, *pw1, *pw2, *pw3;
    cudaGetSymbolAddress(&paggh, g_aggh);
    cudaGetSymbolAddress(&ph16, g_h16);
    cudaGetSymbolAddress(&px16, g_x16);
    cudaGetSymbolAddress(&pt416, g_t416);
    cudaGetSymbolAddress(&pagg4, g_agg4);
    cudaGetSymbolAddress(&pw1, g_wt1);
    cudaGetSymbolAddress(&pw2, g_wt2);
    cudaGetSymbolAddress(&pw3, g_wt3);
    __half2* aggh = (__half2*)paggh;
    __half2* h16  = (__half2*)ph16;
    __half2* x16  = (__half2*)px16;
    __half2* t416 = (__half2*)pt416;
    float*   agg4 = (float*)pagg4;
    __half*  wt1  = (__half*)pw1;
    __half*  wt2  = (__half*)pw2;
    __half*  wt3  = (__half*)pw3;

    const int TB = 256;
    // --- degree + norms + CSR (by destination) ---
    k_zero_deg<<<(N + TB - 1) / TB, TB>>>(N);
    k_deg<<<(E + TB - 1) / TB, TB>>>(dst, E);
    k_inv<<<(N + TB - 1) / TB, TB>>>(N);
    k_blocksum<<<SCAN_BLOCKS, 1024>>>(N);
    k_scanbsums<<<1, 64>>>(N);
    k_scan_apply<<<SCAN_BLOCKS, 1024>>>(N);
    k_scatter<<<(E + TB - 1) / TB, TB>>>(src, dst, E);

    // weight prep (independent of graph work)
    k_wt<<<dim3(4, 8), dim3(32, 8)>>>(W1, wt1, 128, 256);
    k_wt<<<dim3(8, 8), dim3(32, 8)>>>(W2, wt2, 256, 256);
    k_wt<<<dim3(8, 8), dim3(32, 8)>>>(W3, wt3, 256, 256);

    // x -> fp16
    k_f2h<<<(N * 64 + TB - 1) / TB, TB>>>(x, x16, N * 64);

    dim3 gemm_grid(2, (N + 127) / 128);

    // --- Layer 1: aggregate x16 (128-dim), fp16 GEMM+ReLU -> h1 (fp16) ---
    k_gather_agg_h<64, 64><<<N, 64>>>(x16, aggh);
    k_hgemm<<<gemm_grid, 256>>>((const __half*)aggh, wt1, b1, h16, N, FDIM_IN, 1);

    // --- Layer 2 ---
    k_gather_agg_h<128, 128><<<N, 128>>>(h16, aggh);
    k_hgemm<<<gemm_grid, 256>>>((const __half*)aggh, wt2, b2, h16, N, HID, 1);

    // --- Layer 3 ---
    k_gather_agg_h<128, 128><<<N, 128>>>(h16, aggh);
    k_hgemm<<<gemm_grid, 256>>>((const __half*)aggh, wt3, b3, h16, N, HID, 1);

    // --- Layer 4: GEMM to 40 dims (fp16), aggregate, log_softmax ---
    k_gemm40<<<(N + 3) / 4, 160>>>((const __half*)h16, W4, (__half*)t416, N);
    k_gather_agg_w<20><<<(N + 7) / 8, 256>>>(t416, agg4, N);
    k_logsoftmax40<<<(N * 32 + TB - 1) / TB, TB>>>(b4, out, N);
}

// round 9
// speedup vs baseline: 3.7691x; 1.5487x over previous
#include <cuda_runtime.h>
#include <cuda_fp16.h>
#include <math.h>
#include <stdint.h>

#define NNODES 50000
#define NEDGES 1600000
#define FDIM_IN 128
#define HID 256
#define NCLS 40
#define SCAN_BLOCKS 49

// -------- scratch (no allocation allowed; __device__ globals) --------
__device__ int     g_deg[NNODES];
__device__ float   g_inv[NNODES];
__device__ int     g_rowstart[NNODES + 1];
__device__ int     g_cursor[NNODES];
__device__ int     g_bsum[SCAN_BLOCKS];
__device__ int     g_boff[SCAN_BLOCKS];
__device__ int     g_csr_src[NEDGES];
__device__ float   g_csr_w[NEDGES];
__device__ __half2 g_aggh[(size_t)NNODES * (HID/2)];   // aggregation out (fp16, GEMM A)
__device__ __half2 g_h16[(size_t)NNODES * (HID/2)];    // GEMM out (fp16, gather in)
__device__ __half2 g_x16[(size_t)NNODES * (FDIM_IN/2)];
__device__ __half2 g_t4h[(size_t)NNODES * 64];         // layer-4 logits, 128-half rows
__device__ __half  g_wt1[256 * 128];                   // W1^T fp16 [n][k]
__device__ __half  g_wt2[256 * 256];
__device__ __half  g_wt3[256 * 256];
__device__ __half  g_wt4[128 * 256];                   // W4^T padded to 128 rows
__device__ float   g_zbias[128];                       // zero-initialized

// -------- degree / normalization --------
__global__ void k_zero_deg(int n) {
    int i = blockIdx.x * blockDim.x + threadIdx.x;
    if (i < n) g_deg[i] = 0;
}

__global__ void k_deg(const int* __restrict__ dst, int E) {
    int e = blockIdx.x * blockDim.x + threadIdx.x;
    if (e < E) atomicAdd(&g_deg[dst[e]], 1);
}

__global__ void k_inv(int n) {
    int i = blockIdx.x * blockDim.x + threadIdx.x;
    if (i < n) g_inv[i] = rsqrtf((float)g_deg[i] + 1.0f);
}

// -------- 3-phase parallel exclusive scan of g_deg --------
__global__ void __launch_bounds__(1024)
k_blocksum(int n) {
    __shared__ int wsum[32];
    int i = blockIdx.x * 1024 + threadIdx.x;
    int lane = threadIdx.x & 31, wid = threadIdx.x >> 5;
    int v = (i < n) ? g_deg[i] : 0;
#pragma unroll
    for (int o = 16; o > 0; o >>= 1) v += __shfl_xor_sync(0xFFFFFFFF, v, o);
    if (lane == 0) wsum[wid] = v;
    __syncthreads();
    if (wid == 0) {
        int s = wsum[lane];
#pragma unroll
        for (int o = 16; o > 0; o >>= 1) s += __shfl_xor_sync(0xFFFFFFFF, s, o);
        if (lane == 0) g_bsum[blockIdx.x] = s;
    }
}

__global__ void k_scanbsums(int n) {
    __shared__ int sm[64];
    int tid = threadIdx.x;
    int v = (tid < SCAN_BLOCKS) ? g_bsum[tid] : 0;
    sm[tid] = v;
    __syncthreads();
    for (int o = 1; o < 64; o <<= 1) {
        int t = (tid >= o) ? sm[tid - o] : 0;
        __syncthreads();
        sm[tid] += t;
        __syncthreads();
    }
    if (tid < SCAN_BLOCKS) g_boff[tid] = sm[tid] - v;  // exclusive
    if (tid == 63) g_rowstart[n] = sm[63];
}

__global__ void __launch_bounds__(1024)
k_scan_apply(int n) {
    __shared__ int wsum[32];
    int i = blockIdx.x * 1024 + threadIdx.x;
    int lane = threadIdx.x & 31, wid = threadIdx.x >> 5;
    int orig = (i < n) ? g_deg[i] : 0;
    int v = orig;
#pragma unroll
    for (int o = 1; o < 32; o <<= 1) {
        int u = __shfl_up_sync(0xFFFFFFFF, v, o);
        if (lane >= o) v += u;
    }
    if (lane == 31) wsum[wid] = v;
    __syncthreads();
    if (wid == 0) {
        int s = wsum[lane];
#pragma unroll
        for (int o = 1; o < 32; o <<= 1) {
            int u = __shfl_up_sync(0xFFFFFFFF, s, o);
            if (lane >= o) s += u;
        }
        wsum[lane] = s;
    }
    __syncthreads();
    int warpoff = (wid > 0) ? wsum[wid - 1] : 0;
    int excl = g_boff[blockIdx.x] + warpoff + (v - orig);
    if (i < n) { g_rowstart[i] = excl; g_cursor[i] = excl; }
}

__global__ void k_scatter(const int* __restrict__ src, const int* __restrict__ dst, int E) {
    int e = blockIdx.x * blockDim.x + threadIdx.x;
    if (e >= E) return;
    int s = src[e];
    int d = dst[e];
    int pos = atomicAdd(&g_cursor[d], 1);
    g_csr_src[pos] = s;
    g_csr_w[pos]   = g_inv[s] * g_inv[d];
}

// -------- fp32 -> fp16 convert (x) --------
__global__ void k_f2h(const float* __restrict__ x, __half2* __restrict__ o, int n2) {
    int i = blockIdx.x * blockDim.x + threadIdx.x;
    if (i >= n2) return;
    float2 v = ((const float2*)x)[i];
    o[i] = __float22half2_rn(v);
}

// -------- weight transpose + fp16 convert: Wt[n][k] = (half)W[k][n] --------
__global__ void k_wt(const float* __restrict__ W, __half* __restrict__ Wt, int K, int Nc) {
    __shared__ float t[32][33];
    int k0 = blockIdx.x * 32, n0 = blockIdx.y * 32;
    int tx = threadIdx.x, ty = threadIdx.y;  // 32 x 8
    for (int i = ty; i < 32; i += 8)
        t[i][tx] = W[(size_t)(k0 + i) * Nc + n0 + tx];
    __syncthreads();
    for (int i = ty; i < 32; i += 8)
        Wt[(size_t)(n0 + i) * K + k0 + tx] = __float2half_rn(t[tx][i]);
}

// W4 [256][40] -> Wt4 [128][256] fp16, rows >= 40 zero
__global__ void k_wt4(const float* __restrict__ W4, __half* __restrict__ Wt4) {
    int idx = blockIdx.x * blockDim.x + threadIdx.x;
    if (idx >= 128 * 256) return;
    int n = idx >> 8, k = idx & 255;
    float v = (n < NCLS) ? W4[(size_t)k * NCLS + n] : 0.0f;
    Wt4[idx] = __float2half_rn(v);
}

// -------- fp16 accumulate helpers (functions, not macros!) --------
__device__ __forceinline__ void acc8(float* a, uint4 v, float wt) {
    float2 t;
    t = __half22float2(*(__half2*)&v.x); a[0] += wt * t.x; a[1] += wt * t.y;
    t = __half22float2(*(__half2*)&v.y); a[2] += wt * t.x; a[3] += wt * t.y;
    t = __half22float2(*(__half2*)&v.z); a[4] += wt * t.x; a[5] += wt * t.y;
    t = __half22float2(*(__half2*)&v.w); a[6] += wt * t.x; a[7] += wt * t.y;
}

__device__ __forceinline__ void acc4(float* a, uint2 v, float wt) {
    float2 t;
    t = __half22float2(*(__half2*)&v.x); a[0] += wt * t.x; a[1] += wt * t.y;
    t = __half22float2(*(__half2*)&v.y); a[2] += wt * t.x; a[3] += wt * t.y;
}

// ======== warp-per-node gather aggregation, shuffle-broadcast metadata ========
// 256-wide rows: lane owns uint4 = 8 halves. agg = self*inv^2 + sum w_j * h[src_j].
__global__ void __launch_bounds__(256)
k_gagg256(const uint4* __restrict__ h, uint4* __restrict__ agg, int n) {
    int warp = (blockIdx.x * blockDim.x + threadIdx.x) >> 5;
    int lane = threadIdx.x & 31;
    if (warp >= n) return;
    float iv = g_inv[warp]; float iv2 = iv * iv;
    float a[8];
    {
        uint4 sv = __ldg(h + (size_t)warp * 32 + lane);
        float2 t;
        t = __half22float2(*(__half2*)&sv.x); a[0] = t.x * iv2; a[1] = t.y * iv2;
        t = __half22float2(*(__half2*)&sv.y); a[2] = t.x * iv2; a[3] = t.y * iv2;
        t = __half22float2(*(__half2*)&sv.z); a[4] = t.x * iv2; a[5] = t.y * iv2;
        t = __half22float2(*(__half2*)&sv.w); a[6] = t.x * iv2; a[7] = t.y * iv2;
    }
    int j = g_rowstart[warp], end = g_rowstart[warp + 1];
    while (j < end) {
        int cnt = end - j; if (cnt > 32) cnt = 32;
        int si = 0; float wi = 0.0f;
        if (lane < cnt) { si = g_csr_src[j + lane]; wi = g_csr_w[j + lane]; }
        int e = 0;
        for (; e + 4 <= cnt; e += 4) {
            int   s0 = __shfl_sync(0xFFFFFFFF, si, e);
            int   s1 = __shfl_sync(0xFFFFFFFF, si, e + 1);
            int   s2 = __shfl_sync(0xFFFFFFFF, si, e + 2);
            int   s3 = __shfl_sync(0xFFFFFFFF, si, e + 3);
            float w0 = __shfl_sync(0xFFFFFFFF, wi, e);
            float w1 = __shfl_sync(0xFFFFFFFF, wi, e + 1);
            float w2 = __shfl_sync(0xFFFFFFFF, wi, e + 2);
            float w3 = __shfl_sync(0xFFFFFFFF, wi, e + 3);
            uint4 v0 = __ldg(h + (size_t)s0 * 32 + lane);
            uint4 v1 = __ldg(h + (size_t)s1 * 32 + lane);
            uint4 v2 = __ldg(h + (size_t)s2 * 32 + lane);
            uint4 v3 = __ldg(h + (size_t)s3 * 32 + lane);
            acc8(a, v0, w0); acc8(a, v1, w1); acc8(a, v2, w2); acc8(a, v3, w3);
        }
        for (; e < cnt; e++) {
            int   s = __shfl_sync(0xFFFFFFFF, si, e);
            float w = __shfl_sync(0xFFFFFFFF, wi, e);
            uint4 v = __ldg(h + (size_t)s * 32 + lane);
            acc8(a, v, w);
        }
        j += 32;
    }
    uint4 o;
    __half2 p;
    p = __float22half2_rn(make_float2(a[0], a[1])); o.x = *(uint32_t*)&p;
    p = __float22half2_rn(make_float2(a[2], a[3])); o.y = *(uint32_t*)&p;
    p = __float22half2_rn(make_float2(a[4], a[5])); o.z = *(uint32_t*)&p;
    p = __float22half2_rn(make_float2(a[6], a[7])); o.w = *(uint32_t*)&p;
    agg[(size_t)warp * 32 + lane] = o;
}

// 128-wide rows: lane owns uint2 = 4 halves.
__global__ void __launch_bounds__(256)
k_gagg128(const uint2* __restrict__ h, uint2* __restrict__ agg, int n) {
    int warp = (blockIdx.x * blockDim.x + threadIdx.x) >> 5;
    int lane = threadIdx.x & 31;
    if (warp >= n) return;
    float iv = g_inv[warp]; float iv2 = iv * iv;
    float a[4];
    {
        uint2 sv = __ldg(h + (size_t)warp * 32 + lane);
        float2 t;
        t = __half22float2(*(__half2*)&sv.x); a[0] = t.x * iv2; a[1] = t.y * iv2;
        t = __half22float2(*(__half2*)&sv.y); a[2] = t.x * iv2; a[3] = t.y * iv2;
    }
    int j = g_rowstart[warp], end = g_rowstart[warp + 1];
    while (j < end) {
        int cnt = end - j; if (cnt > 32) cnt = 32;
        int si = 0; float wi = 0.0f;
        if (lane < cnt) { si = g_csr_src[j + lane]; wi = g_csr_w[j + lane]; }
        int e = 0;
        for (; e + 4 <= cnt; e += 4) {
            int   s0 = __shfl_sync(0xFFFFFFFF, si, e);
            int   s1 = __shfl_sync(0xFFFFFFFF, si, e + 1);
            int   s2 = __shfl_sync(0xFFFFFFFF, si, e + 2);
            int   s3 = __shfl_sync(0xFFFFFFFF, si, e + 3);
            float w0 = __shfl_sync(0xFFFFFFFF, wi, e);
            float w1 = __shfl_sync(0xFFFFFFFF, wi, e + 1);
            float w2 = __shfl_sync(0xFFFFFFFF, wi, e + 2);
            float w3 = __shfl_sync(0xFFFFFFFF, wi, e + 3);
            uint2 v0 = __ldg(h + (size_t)s0 * 32 + lane);
            uint2 v1 = __ldg(h + (size_t)s1 * 32 + lane);
            uint2 v2 = __ldg(h + (size_t)s2 * 32 + lane);
            uint2 v3 = __ldg(h + (size_t)s3 * 32 + lane);
            acc4(a, v0, w0); acc4(a, v1, w1); acc4(a, v2, w2); acc4(a, v3, w3);
        }
        for (; e < cnt; e++) {
            int   s = __shfl_sync(0xFFFFFFFF, si, e);
            float w = __shfl_sync(0xFFFFFFFF, wi, e);
            uint2 v = __ldg(h + (size_t)s * 32 + lane);
            acc4(a, v, w);
        }
        j += 32;
    }
    uint2 o;
    __half2 p;
    p = __float22half2_rn(make_float2(a[0], a[1])); o.x = *(uint32_t*)&p;
    p = __float22half2_rn(make_float2(a[2], a[3])); o.y = *(uint32_t*)&p;
    agg[(size_t)warp * 32 + lane] = o;
}

// ======== fused layer-4: 40-wide gather + bias + log_softmax, warp per node ====
// t4 rows are 128 halves (64 half2); only first 20 half2 are real logits.
__global__ void __launch_bounds__(256)
k_agg40sm(const __half2* __restrict__ t4, const float* __restrict__ b4,
          float* __restrict__ out, int n) {
    int warp = (blockIdx.x * blockDim.x + threadIdx.x) >> 5;
    int lane = threadIdx.x & 31;
    if (warp >= n) return;
    bool act = lane < 20;
    int f = act ? lane : 19;
    float iv = g_inv[warp]; float iv2 = iv * iv;
    float2 sv = __half22float2(__ldg(t4 + (size_t)warp * 64 + f));
    float ax = sv.x * iv2, ay = sv.y * iv2;
    int j = g_rowstart[warp], end = g_rowstart[warp + 1];
    while (j < end) {
        int cnt = end - j; if (cnt > 32) cnt = 32;
        int si = 0; float wi = 0.0f;
        if (lane < cnt) { si = g_csr_src[j + lane]; wi = g_csr_w[j + lane]; }
        for (int e = 0; e < cnt; e++) {
            int   s = __shfl_sync(0xFFFFFFFF, si, e);
            float w = __shfl_sync(0xFFFFFFFF, wi, e);
            float2 v = __half22float2(__ldg(t4 + (size_t)s * 64 + f));
            ax += w * v.x; ay += w * v.y;
        }
        j += 32;
    }
    ax += b4[2 * f]; ay += b4[2 * f + 1];
    float m = act ? fmaxf(ax, ay) : -INFINITY;
#pragma unroll
    for (int o = 16; o > 0; o >>= 1) m = fmaxf(m, __shfl_xor_sync(0xFFFFFFFF, m, o));
    float s = act ? (__expf(ax - m) + __expf(ay - m)) : 0.0f;
#pragma unroll
    for (int o = 16; o > 0; o >>= 1) s += __shfl_xor_sync(0xFFFFFFFF, s, o);
    float l = m + __logf(s);
    if (act) *(float2*)(out + (size_t)warp * NCLS + 2 * f) = make_float2(ax - l, ay - l);
}

// -------- fp16 tensor-core GEMM: C[M,BN@bn] = A[M,K] @ Bt[.,K]^T (+bias, relu) ----
__device__ __forceinline__ void mma_f16(float* c, const uint32_t* a, const uint32_t* b) {
    asm volatile(
        "mma.sync.aligned.m16n8k16.row.col.f32.f16.f16.f32 "
        "{%0,%1,%2,%3}, {%4,%5,%6,%7}, {%8,%9}, {%0,%1,%2,%3};"
        : "+f"(c[0]), "+f"(c[1]), "+f"(c[2]), "+f"(c[3])
        : "r"(a[0]), "r"(a[1]), "r"(a[2]), "r"(a[3]), "r"(b[0]), "r"(b[1]));
}

#define HPAD 40   // halves per smem row (32 data + 8 pad) -> conflict-free frag loads

__global__ void __launch_bounds__(256)
k_hgemm(const __half* __restrict__ A, const __half* __restrict__ Bt,
        const float* __restrict__ bias, __half2* __restrict__ C16,
        int M, int K, int relu, int ldc) {
    __shared__ __half As[128 * HPAD];
    __shared__ __half Bs[128 * HPAD];
    int tid = threadIdx.x;
    int bm = blockIdx.y * 128, bn = blockIdx.x * 128;
    int lane = tid & 31, w = tid >> 5;
    int wm = (w & 1) * 64, wn = (w >> 1) * 32;
    int g = lane >> 2, tg = lane & 3;

    float acc[4][4][4];
#pragma unroll
    for (int mt = 0; mt < 4; mt++)
#pragma unroll
        for (int nt = 0; nt < 4; nt++)
#pragma unroll
            for (int i = 0; i < 4; i++) acc[mt][nt][i] = 0.0f;

    int row0 = tid >> 2;          // 0..63
    int cc   = (tid & 3) * 8;     // half offset 0,8,16,24

    int KT = K >> 5;
    uint4 apf[2], bpf[2], zero4 = make_uint4(0, 0, 0, 0);

#pragma unroll
    for (int i = 0; i < 2; i++) {
        int r = row0 + i * 64;
        apf[i] = (bm + r < M) ? *(const uint4*)(A + (size_t)(bm + r) * K + cc) : zero4;
        bpf[i] = *(const uint4*)(Bt + (size_t)(bn + r) * K + cc);
    }

    for (int kt = 0; kt < KT; kt++) {
#pragma unroll
        for (int i = 0; i < 2; i++) {
            int r = row0 + i * 64;
            *(uint4*)&As[r * HPAD + cc] = apf[i];
            *(uint4*)&Bs[r * HPAD + cc] = bpf[i];
        }
        __syncthreads();

        if (kt + 1 < KT) {
            int kofs = (kt + 1) * 32;
#pragma unroll
            for (int i = 0; i < 2; i++) {
                int r = row0 + i * 64;
                apf[i] = (bm + r < M) ? *(const uint4*)(A + (size_t)(bm + r) * K + kofs + cc) : zero4;
                bpf[i] = *(const uint4*)(Bt + (size_t)(bn + r) * K + kofs + cc);
            }
        }

#pragma unroll
        for (int kk = 0; kk < 32; kk += 16) {
            uint32_t af[4][4], bf[4][2];
#pragma unroll
            for (int mt = 0; mt < 4; mt++) {
                int base = (wm + mt * 16 + g) * HPAD + kk + 2 * tg;
                af[mt][0] = *(const uint32_t*)&As[base];
                af[mt][1] = *(const uint32_t*)&As[base + 8 * HPAD];
                af[mt][2] = *(const uint32_t*)&As[base + 8];
                af[mt][3] = *(const uint32_t*)&As[base + 8 * HPAD + 8];
            }
#pragma unroll
            for (int nt = 0; nt < 4; nt++) {
                int base = (wn + nt * 8 + g) * HPAD + kk + 2 * tg;
                bf[nt][0] = *(const uint32_t*)&Bs[base];
                bf[nt][1] = *(const uint32_t*)&Bs[base + 8];
            }
#pragma unroll
            for (int mt = 0; mt < 4; mt++)
#pragma unroll
                for (int nt = 0; nt < 4; nt++)
                    mma_f16(acc[mt][nt], af[mt], bf[nt]);
        }
        __syncthreads();
    }

#pragma unroll
    for (int mt = 0; mt < 4; mt++) {
        int r0 = bm + wm + mt * 16 + g;
#pragma unroll
        for (int nt = 0; nt < 4; nt++) {
            int col = bn + wn + nt * 8 + 2 * tg;
            float bx = bias[col], by = bias[col + 1];
            float2 v0, v1;
            v0.x = acc[mt][nt][0] + bx; v0.y = acc[mt][nt][1] + by;
            v1.x = acc[mt][nt][2] + bx; v1.y = acc[mt][nt][3] + by;
            if (relu) {
                v0.x = fmaxf(v0.x, 0.f); v0.y = fmaxf(v0.y, 0.f);
                v1.x = fmaxf(v1.x, 0.f); v1.y = fmaxf(v1.y, 0.f);
            }
            if (r0 < M)     C16[((size_t)r0 * ldc + col) >> 1] = __float22half2_rn(v0);
            if (r0 + 8 < M) C16[((size_t)(r0 + 8) * ldc + col) >> 1] = __float22half2_rn(v1);
        }
    }
}

// ---------------------------------------------------------------
extern "C" void kernel_launch(void* const* d_in, const int* in_sizes, int n_in,
                              void* d_out, int out_size) {
    const float* x  = (const float*)d_in[0];
    const int*   ei = (const int*)d_in[1];
    const float* W1 = (const float*)d_in[2]; const float* b1 = (const float*)d_in[3];
    const float* W2 = (const float*)d_in[4]; const float* b2 = (const float*)d_in[5];
    const float* W3 = (const float*)d_in[6]; const float* b3 = (const float*)d_in[7];
    const float* W4 = (const float*)d_in[8]; const float* b4 = (const float*)d_in[9];
    float* out = (float*)d_out;

    int N = in_sizes[0] / FDIM_IN;
    int E = in_sizes[1] / 2;
    const int* src = ei;
    const int* dst = ei + E;

    void *paggh, *ph16, *px16, *pt4h, *pw1, *pw2, *pw3, *pw4, *pzb;
    cudaGetSymbolAddress(&paggh, g_aggh);
    cudaGetSymbolAddress(&ph16, g_h16);
    cudaGetSymbolAddress(&px16, g_x16);
    cudaGetSymbolAddress(&pt4h, g_t4h);
    cudaGetSymbolAddress(&pw1, g_wt1);
    cudaGetSymbolAddress(&pw2, g_wt2);
    cudaGetSymbolAddress(&pw3, g_wt3);
    cudaGetSymbolAddress(&pw4, g_wt4);
    cudaGetSymbolAddress(&pzb, g_zbias);
    __half2* aggh = (__half2*)paggh;
    __half2* h16  = (__half2*)ph16;
    __half2* x16  = (__half2*)px16;
    __half2* t4h  = (__half2*)pt4h;
    __half*  wt1  = (__half*)pw1;
    __half*  wt2  = (__half*)pw2;
    __half*  wt3  = (__half*)pw3;
    __half*  wt4  = (__half*)pw4;
    float*   zb   = (float*)pzb;

    const int TB = 256;
    // --- degree + norms + CSR (by destination) ---
    k_zero_deg<<<(N + TB - 1) / TB, TB>>>(N);
    k_deg<<<(E + TB - 1) / TB, TB>>>(dst, E);
    k_inv<<<(N + TB - 1) / TB, TB>>>(N);
    k_blocksum<<<SCAN_BLOCKS, 1024>>>(N);
    k_scanbsums<<<1, 64>>>(N);
    k_scan_apply<<<SCAN_BLOCKS, 1024>>>(N);
    k_scatter<<<(E + TB - 1) / TB, TB>>>(src, dst, E);

    // weight prep + x conversion (independent of graph work)
    k_wt<<<dim3(4, 8), dim3(32, 8)>>>(W1, wt1, 128, 256);
    k_wt<<<dim3(8, 8), dim3(32, 8)>>>(W2, wt2, 256, 256);
    k_wt<<<dim3(8, 8), dim3(32, 8)>>>(W3, wt3, 256, 256);
    k_wt4<<<(128 * 256 + TB - 1) / TB, TB>>>(W4, wt4);
    k_f2h<<<(N * 64 + TB - 1) / TB, TB>>>(x, x16, N * 64);

    dim3 gemm_grid(2, (N + 127) / 128);
    int  gwarps = (N * 32 + TB - 1) / TB;   // warp-per-node grids

    // --- Layer 1: aggregate x16 (128-wide), fp16 GEMM+ReLU -> h1 (fp16) ---
    k_gagg128<<<gwarps, TB>>>((const uint2*)x16, (uint2*)aggh, N);
    k_hgemm<<<gemm_grid, 256>>>((const __half*)aggh, wt1, b1, h16, N, FDIM_IN, 1, 256);

    // --- Layer 2 ---
    k_gagg256<<<gwarps, TB>>>((const uint4*)h16, (uint4*)aggh, N);
    k_hgemm<<<gemm_grid, 256>>>((const __half*)aggh, wt2, b2, h16, N, HID, 1, 256);

    // --- Layer 3 ---
    k_gagg256<<<gwarps, TB>>>((const uint4*)h16, (uint4*)aggh, N);
    k_hgemm<<<gemm_grid, 256>>>((const __half*)aggh, wt3, b3, h16, N, HID, 1, 256);

    // --- Layer 4: fp16 GEMM -> 128-padded logits, fused gather+softmax ---
    k_hgemm<<<dim3(1, (N + 127) / 128), 256>>>((const __half*)h16, wt4, zb, t4h, N, HID, 0, 128);
    k_agg40sm<<<gwarps, TB>>>(t4h, b4, out, N);
}